// round 7
// baseline (speedup 1.0000x reference)
#include <cuda_runtime.h>
#include <math.h>
#include <cstdint>

#define Bb   16
#define Tt   4096
#define Cc   512
#define Ee   256
#define NE   1024
#define NTOK (Bb*Tt)

// ---- scratch (static device memory) ----
// x fragments: per 64-token group: [ks(32)][k(8)][tm(4)][slot(8)] float4
//   float4 = {hi[m], hi[m+8], lo[m], lo[m+8]} for one k(=e)
__device__ __align__(16) float g_xf[(size_t)NTOK * Ee * 2];
// embed fragments: per 128-code group: [ks(32)][kp(4)][tn(16)][slot(8)] float4
__device__ __align__(16) float g_ef[(size_t)NE * Ee * 2];
// proj-weight fragments: [ks(64)][kp(4)][tn(32)][slot(8)] float4
__device__ __align__(16) float g_wf[(size_t)Ee * Cc * 2];
__device__ float  g_enorm[NE];
__device__ float  g_xn[NTOK];       // per-token ||x||^2
__device__ int    g_idx[NTOK];
__device__ int    g_hist[NE];
__device__ double g_mse;            // sum of d2_min over tokens

// ---------------- helpers ----------------
__device__ __forceinline__ uint32_t smem_u32(const void* p) {
    uint32_t a;
    asm("{ .reg .u64 t; cvta.to.shared.u64 t, %1; cvt.u32.u64 %0, t; }" : "=r"(a) : "l"(p));
    return a;
}
__device__ __forceinline__ float tf32_hi(float x) {
    uint32_t b; asm("cvt.rna.tf32.f32 %0, %1;" : "=r"(b) : "f"(x));
    return __uint_as_float(b);
}
__device__ __forceinline__ void mma1688(float* d, uint32_t a0, uint32_t a1,
                                        uint32_t a2, uint32_t a3,
                                        uint32_t b0, uint32_t b1) {
    asm volatile(
        "mma.sync.aligned.m16n8k8.row.col.f32.tf32.tf32.f32 "
        "{%0,%1,%2,%3}, {%4,%5,%6,%7}, {%8,%9}, {%0,%1,%2,%3};"
        : "+f"(d[0]), "+f"(d[1]), "+f"(d[2]), "+f"(d[3])
        : "r"(a0), "r"(a1), "r"(a2), "r"(a3), "r"(b0), "r"(b1));
}
__device__ __forceinline__ void cp16(uint32_t s, const void* g) {
    asm volatile("cp.async.cg.shared.global [%0], [%1], 16;" :: "r"(s), "l"(g));
}
#define CP_COMMIT() asm volatile("cp.async.commit_group;" ::: "memory")
#define CP_WAIT1()  asm volatile("cp.async.wait_group 1;" ::: "memory")
#define CP_WAIT0()  asm volatile("cp.async.wait_group 0;" ::: "memory")

// ---------------------------------------------------------------
// init: ||e||^2, embed hi/lo fragment layout, zero hist/mse
// ---------------------------------------------------------------
__global__ void k_init(const float* __restrict__ embed) {
    int c = blockIdx.x;                 // 1024 blocks, 256 threads
    int e = threadIdx.x;
    float v = embed[(size_t)c * Ee + e];
    float h = tf32_hi(v);
    float l = tf32_hi(v - h);
    int cg = c >> 7, cl = c & 127, tn = cl >> 3, n8 = cl & 7;
    int ks = e >> 3, k8 = e & 7, kp = k8 & 3, half = k8 >> 2;
    int slot = (n8 + 2 * kp) & 7;
    size_t i4 = ((((size_t)cg * 32 + ks) * 4 + kp) * 16 + tn) * 8 + slot;
    g_ef[i4 * 4 + half]     = h;
    g_ef[i4 * 4 + 2 + half] = l;

    float s = v * v;
    __shared__ float red[8];
    for (int o = 16; o > 0; o >>= 1) s += __shfl_down_sync(0xffffffffu, s, o);
    if ((e & 31) == 0) red[e >> 5] = s;
    __syncthreads();
    if (e == 0) {
        float t = 0.f;
        #pragma unroll
        for (int i = 0; i < 8; i++) t += red[i];
        g_enorm[c] = t;
        g_hist[c]  = 0;
        if (c == 0) g_mse = 0.0;
    }
}

// ---------------------------------------------------------------
// winit: proj weight hi/lo fragments (B operand layout)
// ---------------------------------------------------------------
__global__ void k_winit(const float* __restrict__ w) {
    int c = blockIdx.x;                 // 0..511
    int e = threadIdx.x;                // 0..255
    float v = w[(size_t)e * Cc + c];
    float h = tf32_hi(v);
    float l = tf32_hi(v - h);
    int ks = c >> 3, k8 = c & 7, kp = k8 & 3, half = k8 >> 2;
    int tn = e >> 3, n8 = e & 7;
    int slot = (n8 + 2 * kp) & 7;
    size_t i4 = (((size_t)ks * 4 + kp) * 32 + tn) * 8 + slot;
    g_wf[i4 * 4 + half]     = h;
    g_wf[i4 * 4 + 2 + half] = l;
}

// ---------------------------------------------------------------
// projection via mma.sync tf32x3: CTA = 128 tokens x 256 feats
// 512 threads = 16 warps (4m x 4n); warp tile 32 tokens x 64 feats
// ---------------------------------------------------------------
#define PROJ_DYN (32768 + 2 * 65536)
__global__ void __launch_bounds__(512, 1)
k_proj(const float* __restrict__ in, const float* __restrict__ bias) {
    extern __shared__ char dyn[];
    float4* fragA = (float4*)dyn;                                   // 2048 f4
    float4* smB0  = (float4*)(dyn + 32768);                         // 4096 f4
    float4* smB1  = (float4*)(dyn + 98304);                         // 4096 f4
    __shared__ float sBias[256];
    __shared__ float sXn[128];

    int tid  = threadIdx.x;
    int lane = tid & 31, wid = tid >> 5;
    int wm   = wid >> 2, wn = wid & 3;
    int q    = lane >> 2, kq = lane & 3;
    int S    = (q + 2 * kq) & 7;
    int n0   = blockIdx.x * 128;
    int b    = n0 >> 12, t0 = n0 & 4095;
    const float* inb = in + (size_t)b * Cc * Tt + t0;
    uint32_t smBu[2] = { smem_u32(smB0), smem_u32(smB1) };

    if (tid < 256) sBias[tid] = bias[tid];
    if (tid < 128) sXn[tid] = 0.f;

    #define ISSUE_W(ch) do {                                                     \
        const char* _s = (const char*)((const float4*)g_wf + (size_t)(ch)*4096); \
        uint32_t _d = smBu[(ch) & 1];                                            \
        for (int i = tid; i < 4096; i += 512)                                    \
            cp16(_d + (uint32_t)i * 16, _s + (size_t)i * 16);                    \
        CP_COMMIT();                                                             \
    } while (0)

    ISSUE_W(0);
    ISSUE_W(1);

    float acc[2][8][4];
    #pragma unroll
    for (int a = 0; a < 2; a++)
        #pragma unroll
        for (int bb = 0; bb < 8; bb++)
            #pragma unroll
            for (int cix = 0; cix < 4; cix++) acc[a][bb][cix] = 0.f;

    for (int ch = 0; ch < 16; ch++) {
        // ---- A fill: LDG token pair, tf32 split, fragment STS ----
        {
            float v0[4], v1[4];
            #pragma unroll
            for (int it = 0; it < 4; it++) {
                int item = it * 512 + tid;
                int r = item & 7, tm = (item >> 3) & 7, c = item >> 6;
                const float* p = inb + (size_t)(ch * 32 + c) * Tt + tm * 16 + r;
                v0[it] = p[0];
                v1[it] = p[8];
            }
            #pragma unroll
            for (int it = 0; it < 4; it++) {
                int item = it * 512 + tid;
                int r = item & 7, tm = (item >> 3) & 7, c = item >> 6;
                int k8 = c & 7, ksl = c >> 3, kp = k8 & 3, sl = (r + 2 * kp) & 7;
                float h0 = tf32_hi(v0[it]), l0 = tf32_hi(v0[it] - h0);
                float h1 = tf32_hi(v1[it]), l1 = tf32_hi(v1[it] - h1);
                fragA[((ksl * 8 + k8) * 8 + tm) * 8 + sl] = make_float4(h0, h1, l0, l1);
            }
        }
        if (ch < 15) CP_WAIT1(); else CP_WAIT0();
        __syncthreads();
        const float4* B4 = (ch & 1) ? smB1 : smB0;
        #pragma unroll
        for (int ksl = 0; ksl < 4; ksl++) {
            float4 aA[2], aB[2];
            #pragma unroll
            for (int mt = 0; mt < 2; mt++) {
                int tmg = wm * 2 + mt;
                aA[mt] = fragA[((ksl * 8 + kq) * 8 + tmg) * 8 + S];
                aB[mt] = fragA[((ksl * 8 + kq + 4) * 8 + tmg) * 8 + S];
            }
            #pragma unroll
            for (int nt = 0; nt < 8; nt++) {
                float4 bf = B4[((ksl * 4 + kq) * 32 + wn * 8 + nt) * 8 + S];
                uint32_t bh0 = __float_as_uint(bf.x), bh1 = __float_as_uint(bf.y);
                uint32_t bl0 = __float_as_uint(bf.z), bl1 = __float_as_uint(bf.w);
                #pragma unroll
                for (int mt = 0; mt < 2; mt++) {
                    uint32_t ah0 = __float_as_uint(aA[mt].x), ah1 = __float_as_uint(aA[mt].y);
                    uint32_t ah2 = __float_as_uint(aB[mt].x), ah3 = __float_as_uint(aB[mt].y);
                    uint32_t al0 = __float_as_uint(aA[mt].z), al1 = __float_as_uint(aA[mt].w);
                    uint32_t al2 = __float_as_uint(aB[mt].z), al3 = __float_as_uint(aB[mt].w);
                    mma1688(acc[mt][nt], ah0, ah1, ah2, ah3, bh0, bh1);
                    mma1688(acc[mt][nt], ah0, ah1, ah2, ah3, bl0, bl1);
                    mma1688(acc[mt][nt], al0, al1, al2, al3, bh0, bh1);
                }
            }
        }
        __syncthreads();
        if (ch + 2 < 16) ISSUE_W(ch + 2);
    }

    // ---- epilogue: bias, x fragments (k_dist A layout), ||x||^2 ----
    #pragma unroll
    for (int mt = 0; mt < 2; mt++) {
        int tlb = wm * 32 + mt * 16;
        int g   = (n0 >> 6) + (tlb >> 6);
        int tmg = (tlb >> 4) & 3;
        float4* xf4 = (float4*)g_xf + (size_t)g * 8192;
        float xnq = 0.f, xnq8 = 0.f;
        #pragma unroll
        for (int nt = 0; nt < 8; nt++) {
            int e = wn * 64 + nt * 8 + 2 * kq;
            float x0 = acc[mt][nt][0] + sBias[e];
            float x1 = acc[mt][nt][1] + sBias[e + 1];
            float x2 = acc[mt][nt][2] + sBias[e];
            float x3 = acc[mt][nt][3] + sBias[e + 1];
            xnq  += x0 * x0 + x1 * x1;
            xnq8 += x2 * x2 + x3 * x3;
            {
                int k8 = e & 7, ks = e >> 3, kp = k8 & 3, sl = (q + 2 * kp) & 7;
                float h0 = tf32_hi(x0), h2 = tf32_hi(x2);
                xf4[((ks * 8 + k8) * 4 + tmg) * 8 + sl] =
                    make_float4(h0, h2, tf32_hi(x0 - h0), tf32_hi(x2 - h2));
            }
            {
                int e1 = e + 1;
                int k8 = e1 & 7, ks = e1 >> 3, kp = k8 & 3, sl = (q + 2 * kp) & 7;
                float h1 = tf32_hi(x1), h3 = tf32_hi(x3);
                xf4[((ks * 8 + k8) * 4 + tmg) * 8 + sl] =
                    make_float4(h1, h3, tf32_hi(x1 - h1), tf32_hi(x3 - h3));
            }
        }
        xnq  += __shfl_xor_sync(0xffffffffu, xnq, 1);
        xnq  += __shfl_xor_sync(0xffffffffu, xnq, 2);
        xnq8 += __shfl_xor_sync(0xffffffffu, xnq8, 1);
        xnq8 += __shfl_xor_sync(0xffffffffu, xnq8, 2);
        if (kq == 0) {
            atomicAdd(&sXn[tlb + q], xnq);
            atomicAdd(&sXn[tlb + q + 8], xnq8);
        }
    }
    __syncthreads();
    if (tid < 128) g_xn[n0 + tid] = sXn[tid];
}

// ---------------------------------------------------------------
// distance via mma.sync tf32x3: CTA = 64 tokens x all 1024 codes
// 512 threads = 16 warps (4m x 4n); warp tile 16 tokens x 32 codes
// A resident (128KB), B double-buffered cp.async (2x32KB)
// ---------------------------------------------------------------
#define DIST_DYN 202752
__global__ void __launch_bounds__(512, 1)
k_dist() {
    extern __shared__ char dyn[];
    float4* smA  = (float4*)dyn;                        // 8192 f4
    float4* smB0 = (float4*)(dyn + 131072);             // 2048 f4
    float4* smB1 = (float4*)(dyn + 163840);             // 2048 f4
    float*  s_en = (float*)(dyn + 196608);              // 1024 f
    float*  redv = (float*)(dyn + 200704);              // 64*4
    int*    redi = (int*)(dyn + 201728);                // 64*4
    __shared__ float lred[2];

    int tid  = threadIdx.x;
    int wid  = tid >> 5, lane = tid & 31;
    int wm   = wid >> 2, wn = wid & 3;
    int q    = lane >> 2, kq = lane & 3;
    int slot = (q + 2 * kq) & 7;
    int g    = blockIdx.x;                              // token group (64 tokens)
    uint32_t smAu  = smem_u32(smA);
    uint32_t smBu[2] = { smem_u32(smB0), smem_u32(smB1) };

    {
        const char* src = (const char*)((const float4*)g_xf + (size_t)g * 8192);
        for (int i = tid; i < 8192; i += 512)
            cp16(smAu + (uint32_t)i * 16, src + (size_t)i * 16);
        CP_COMMIT();
    }
    for (int i = tid; i < 1024; i += 512) s_en[i] = g_enorm[i];

    #define ISSUE(gc) do {                                                        \
        int _cg = (gc) >> 3, _ch = (gc) & 7;                                      \
        const char* _s = (const char*)((const float4*)g_ef +                      \
                          (size_t)_cg * 16384 + (size_t)_ch * 2048);              \
        uint32_t _d = smBu[(gc) & 1];                                             \
        for (int i = tid; i < 2048; i += 512)                                     \
            cp16(_d + (uint32_t)i * 16, _s + (size_t)i * 16);                     \
        CP_COMMIT();                                                              \
    } while (0)

    ISSUE(0);

    float acc[4][4];
    #pragma unroll
    for (int b = 0; b < 4; b++)
        #pragma unroll
        for (int c = 0; c < 4; c++) acc[b][c] = 0.f;
    float bestv[2]; int besti[2];
    bestv[0] = bestv[1] = 3.0e38f; besti[0] = besti[1] = 0;

    for (int gc = 0; gc < 64; gc++) {
        if (gc + 1 < 64) { ISSUE(gc + 1); CP_WAIT1(); } else { CP_WAIT0(); }
        __syncthreads();
        const float4* B4 = (gc & 1) ? smB1 : smB0;
        int ch = gc & 7;
        #pragma unroll
        for (int ksl = 0; ksl < 4; ksl++) {
            int ks = ch * 4 + ksl;
            float4 aA = smA[(ks * 8 + kq) * 32 + wm * 8 + slot];
            float4 aB = smA[(ks * 8 + kq + 4) * 32 + wm * 8 + slot];
            uint32_t ah0 = __float_as_uint(aA.x), ah1 = __float_as_uint(aA.y);
            uint32_t ah2 = __float_as_uint(aB.x), ah3 = __float_as_uint(aB.y);
            uint32_t al0 = __float_as_uint(aA.z), al1 = __float_as_uint(aA.w);
            uint32_t al2 = __float_as_uint(aB.z), al3 = __float_as_uint(aB.w);
            #pragma unroll
            for (int tn4 = 0; tn4 < 4; tn4++) {
                float4 bf = B4[((ksl * 4 + kq) * 16 + wn * 4 + tn4) * 8 + slot];
                uint32_t bh0 = __float_as_uint(bf.x), bh1 = __float_as_uint(bf.y);
                uint32_t bl0 = __float_as_uint(bf.z), bl1 = __float_as_uint(bf.w);
                mma1688(acc[tn4], ah0, ah1, ah2, ah3, bh0, bh1);
                mma1688(acc[tn4], ah0, ah1, ah2, ah3, bl0, bl1);
                mma1688(acc[tn4], al0, al1, al2, al3, bh0, bh1);
            }
        }
        if ((gc & 7) == 7) {
            int cg = gc >> 3;
            #pragma unroll
            for (int tn4 = 0; tn4 < 4; tn4++) {
                int nb = cg * 128 + wn * 32 + tn4 * 8 + 2 * kq;
                float e0v = s_en[nb], e1v = s_en[nb + 1];
                float s00 = fmaf(-2.0f, acc[tn4][0], e0v);
                float s01 = fmaf(-2.0f, acc[tn4][1], e1v);
                float s10 = fmaf(-2.0f, acc[tn4][2], e0v);
                float s11 = fmaf(-2.0f, acc[tn4][3], e1v);
                if (s00 < bestv[0]) { bestv[0] = s00; besti[0] = nb; }
                if (s01 < bestv[0]) { bestv[0] = s01; besti[0] = nb + 1; }
                if (s10 < bestv[1]) { bestv[1] = s10; besti[1] = nb; }
                if (s11 < bestv[1]) { bestv[1] = s11; besti[1] = nb + 1; }
                acc[tn4][0] = 0.f; acc[tn4][1] = 0.f;
                acc[tn4][2] = 0.f; acc[tn4][3] = 0.f;
            }
        }
        __syncthreads();
    }
    #pragma unroll
    for (int s = 0; s < 2; s++) {
        float v = bestv[s]; int bi = besti[s];
        #pragma unroll
        for (int off = 1; off <= 2; off <<= 1) {
            float ov = __shfl_xor_sync(0xffffffffu, v, off);
            int   oi = __shfl_xor_sync(0xffffffffu, bi, off);
            if (ov < v || (ov == v && oi < bi)) { v = ov; bi = oi; }
        }
        if ((lane & 3) == 0) {
            int row = wm * 16 + s * 8 + q;
            redv[row * 4 + wn] = v;
            redi[row * 4 + wn] = bi;
        }
    }
    __syncthreads();
    float myd2 = 0.f;
    if (tid < 64) {
        float v = redv[tid * 4]; int bi = redi[tid * 4];
        #pragma unroll
        for (int j = 1; j < 4; j++) {
            float ov = redv[tid * 4 + j]; int oi = redi[tid * 4 + j];
            if (ov < v || (ov == v && oi < bi)) { v = ov; bi = oi; }
        }
        int n = g * 64 + tid;
        g_idx[n] = bi;
        atomicAdd(&g_hist[bi], 1);
        myd2 = g_xn[n] + v;                    // ||x||^2 + (||e||^2 - 2x.e)
    }
    for (int o = 16; o > 0; o >>= 1) myd2 += __shfl_down_sync(0xffffffffu, myd2, o);
    if ((tid & 31) == 0 && wid < 2) lred[wid] = myd2;
    __syncthreads();
    if (tid == 0) atomicAdd(&g_mse, (double)(lred[0] + lred[1]));
}

// ---------------------------------------------------------------
// output: z_q_out[b,e,t] = embed[q_idx[b*T+t]][e]  (32x32 transpose)
// ---------------------------------------------------------------
__global__ void k_out(const float* __restrict__ embed, float* __restrict__ out) {
    __shared__ int   qs[32];
    __shared__ float sm[32][33];
    int b  = blockIdx.z;
    int e0 = blockIdx.y * 32;
    int t0 = blockIdx.x * 32;
    int tid = threadIdx.x;
    if (tid < 32) qs[tid] = g_idx[b * Tt + t0 + tid];
    __syncthreads();
    {
        int j = tid >> 3, gg = tid & 7;
        const float4* erow = (const float4*)(embed + (size_t)qs[j] * Ee + e0);
        float4 v = erow[gg];
        sm[j][gg * 4 + 0] = v.x; sm[j][gg * 4 + 1] = v.y;
        sm[j][gg * 4 + 2] = v.z; sm[j][gg * 4 + 3] = v.w;
    }
    __syncthreads();
    int tl = tid & 31, eb = tid >> 5;
    #pragma unroll
    for (int r = 0; r < 4; r++) {
        int el = eb + r * 8;
        out[((size_t)b * Ee + e0 + el) * Tt + t0 + tl] = sm[tl][el];
    }
}

// ---------------------------------------------------------------
// tail scalars
// ---------------------------------------------------------------
__global__ void k_tail(float* __restrict__ out) {
    __shared__ float red[32];
    int tid = threadIdx.x;                     // 1024
    float p = (float)g_hist[tid] / 65536.0f;
    float term = -p * logf(p + 1e-10f);
    for (int o = 16; o > 0; o >>= 1) term += __shfl_down_sync(0xffffffffu, term, o);
    if ((tid & 31) == 0) red[tid >> 5] = term;
    __syncthreads();
    const size_t base = (size_t)Bb * Ee * Tt;
    if (tid == 0) {
        float lp = 0.f;
        #pragma unroll
        for (int i = 0; i < 32; i++) lp += red[i];
        out[base + 0]  = (float)(1.25 * (g_mse / (double)((size_t)NTOK * Ee)));
        out[base + 17] = lp;
    }
    if (tid < 16) out[base + 1 + tid] = (float)(log(1024.0) * 4096.0);
}

// ---------------------------------------------------------------
extern "C" void kernel_launch(void* const* d_in, const int* in_sizes, int n_in,
                              void* d_out, int out_size) {
    const float* inputs = (const float*)d_in[0];   // [16, 512, 4096]
    const float* proj_w = (const float*)d_in[1];   // [256, 512]
    const float* proj_b = (const float*)d_in[2];   // [256]
    const float* embed  = (const float*)d_in[3];   // [1024, 256]
    float* out = (float*)d_out;

    cudaFuncSetAttribute(k_proj, cudaFuncAttributeMaxDynamicSharedMemorySize, PROJ_DYN);
    cudaFuncSetAttribute(k_dist, cudaFuncAttributeMaxDynamicSharedMemorySize, DIST_DYN);

    k_init<<<NE, 256>>>(embed);
    k_winit<<<Cc, 256>>>(proj_w);
    k_proj<<<NTOK / 128, 512, PROJ_DYN>>>(inputs, proj_b);
    k_dist<<<NTOK / 64, 512, DIST_DYN>>>();
    dim3 g3(Tt / 32, Ee / 32, Bb);
    k_out<<<g3, 256>>>(embed, out);
    k_tail<<<1, 1024>>>(out);
}

// round 8
// speedup vs baseline: 1.0038x; 1.0038x over previous
#include <cuda_runtime.h>
#include <math.h>
#include <cstdint>

#define Bb   16
#define Tt   4096
#define Cc   512
#define Ee   256
#define NE   1024
#define NTOK (Bb*Tt)

// ---- scratch (static device memory) ----
// x fragments: per 64-token group: [ks(32)][k(8)][tm(4)][slot(8)] float4
//   float4 = {hi[m], hi[m+8], lo[m], lo[m+8]} for one k(=e)
__device__ __align__(16) float g_xf[(size_t)NTOK * Ee * 2];
// embed fragments: per 128-code group: [ks(32)][kp(4)][tn(16)][slot(8)] float4
__device__ __align__(16) float g_ef[(size_t)NE * Ee * 2];
// proj-weight fragments: [ks(64)][kp(4)][tn(32)][slot(8)] float4
__device__ __align__(16) float g_wf[(size_t)Ee * Cc * 2];
__device__ float  g_enorm[NE];
__device__ float  g_xn[NTOK];       // per-token ||x||^2
__device__ int    g_idx[NTOK];
__device__ int    g_hist[NE];
__device__ double g_mse;            // sum of d2_min over tokens

// ---------------- helpers ----------------
__device__ __forceinline__ uint32_t smem_u32(const void* p) {
    uint32_t a;
    asm("{ .reg .u64 t; cvta.to.shared.u64 t, %1; cvt.u32.u64 %0, t; }" : "=r"(a) : "l"(p));
    return a;
}
__device__ __forceinline__ float tf32_hi(float x) {
    uint32_t b; asm("cvt.rna.tf32.f32 %0, %1;" : "=r"(b) : "f"(x));
    return __uint_as_float(b);
}
__device__ __forceinline__ void mma1688(float* d, uint32_t a0, uint32_t a1,
                                        uint32_t a2, uint32_t a3,
                                        uint32_t b0, uint32_t b1) {
    asm volatile(
        "mma.sync.aligned.m16n8k8.row.col.f32.tf32.tf32.f32 "
        "{%0,%1,%2,%3}, {%4,%5,%6,%7}, {%8,%9}, {%0,%1,%2,%3};"
        : "+f"(d[0]), "+f"(d[1]), "+f"(d[2]), "+f"(d[3])
        : "r"(a0), "r"(a1), "r"(a2), "r"(a3), "r"(b0), "r"(b1));
}
__device__ __forceinline__ void cp16(uint32_t s, const void* g) {
    asm volatile("cp.async.cg.shared.global [%0], [%1], 16;" :: "r"(s), "l"(g));
}
#define CP_COMMIT() asm volatile("cp.async.commit_group;" ::: "memory")
#define CP_WAIT1()  asm volatile("cp.async.wait_group 1;" ::: "memory")
#define CP_WAIT0()  asm volatile("cp.async.wait_group 0;" ::: "memory")

// ---------------------------------------------------------------
// init: ||e||^2, embed hi/lo fragment layout, zero hist/mse
// ---------------------------------------------------------------
__global__ void k_init(const float* __restrict__ embed) {
    int c = blockIdx.x;                 // 1024 blocks, 256 threads
    int e = threadIdx.x;
    float v = embed[(size_t)c * Ee + e];
    float h = tf32_hi(v);
    float l = tf32_hi(v - h);
    int cg = c >> 7, cl = c & 127, tn = cl >> 3, n8 = cl & 7;
    int ks = e >> 3, k8 = e & 7, kp = k8 & 3, half = k8 >> 2;
    int slot = (n8 + 2 * kp) & 7;
    size_t i4 = ((((size_t)cg * 32 + ks) * 4 + kp) * 16 + tn) * 8 + slot;
    g_ef[i4 * 4 + half]     = h;
    g_ef[i4 * 4 + 2 + half] = l;

    float s = v * v;
    __shared__ float red[8];
    for (int o = 16; o > 0; o >>= 1) s += __shfl_down_sync(0xffffffffu, s, o);
    if ((e & 31) == 0) red[e >> 5] = s;
    __syncthreads();
    if (e == 0) {
        float t = 0.f;
        #pragma unroll
        for (int i = 0; i < 8; i++) t += red[i];
        g_enorm[c] = t;
        g_hist[c]  = 0;
        if (c == 0) g_mse = 0.0;
    }
}

// ---------------------------------------------------------------
// winit: proj weight hi/lo fragments (B operand layout)
// ---------------------------------------------------------------
__global__ void k_winit(const float* __restrict__ w) {
    int c = blockIdx.x;                 // 0..511
    int e = threadIdx.x;                // 0..255
    float v = w[(size_t)e * Cc + c];
    float h = tf32_hi(v);
    float l = tf32_hi(v - h);
    int ks = c >> 3, k8 = c & 7, kp = k8 & 3, half = k8 >> 2;
    int tn = e >> 3, n8 = e & 7;
    int slot = (n8 + 2 * kp) & 7;
    size_t i4 = (((size_t)ks * 4 + kp) * 32 + tn) * 8 + slot;
    g_wf[i4 * 4 + half]     = h;
    g_wf[i4 * 4 + 2 + half] = l;
}

// ---------------------------------------------------------------
// projection via mma.sync tf32x3: CTA = 128 tokens x 256 feats
// 256 threads = 8 warps (2m x 4n); warp tile 64 tokens x 64 feats
// ---------------------------------------------------------------
#define PROJ_DYN (32768 + 2 * 65536)
__global__ void __launch_bounds__(256, 1)
k_proj(const float* __restrict__ in, const float* __restrict__ bias) {
    extern __shared__ char dyn[];
    float4* fragA = (float4*)dyn;                                   // 2048 f4
    float4* smB0  = (float4*)(dyn + 32768);                         // 4096 f4
    float4* smB1  = (float4*)(dyn + 98304);                         // 4096 f4
    __shared__ float sBias[256];
    __shared__ float sXn[128];

    int tid  = threadIdx.x;
    int lane = tid & 31, wid = tid >> 5;
    int wm   = wid >> 2, wn = wid & 3;
    int q    = lane >> 2, kq = lane & 3;
    int S    = (q + 2 * kq) & 7;
    int n0   = blockIdx.x * 128;
    int b    = n0 >> 12, t0 = n0 & 4095;
    const float* inb = in + (size_t)b * Cc * Tt + t0;
    uint32_t smBu[2] = { smem_u32(smB0), smem_u32(smB1) };

    sBias[tid] = bias[tid];
    if (tid < 128) sXn[tid] = 0.f;

    #define ISSUE_W(ch) do {                                                     \
        const char* _s = (const char*)((const float4*)g_wf + (size_t)(ch)*4096); \
        uint32_t _d = smBu[(ch) & 1];                                            \
        for (int i = tid; i < 4096; i += 256)                                    \
            cp16(_d + (uint32_t)i * 16, _s + (size_t)i * 16);                    \
        CP_COMMIT();                                                             \
    } while (0)

    ISSUE_W(0);
    ISSUE_W(1);

    float acc[4][8][4];
    #pragma unroll
    for (int a = 0; a < 4; a++)
        #pragma unroll
        for (int bb = 0; bb < 8; bb++)
            #pragma unroll
            for (int cix = 0; cix < 4; cix++) acc[a][bb][cix] = 0.f;

    for (int ch = 0; ch < 16; ch++) {
        // ---- A fill: LDG token pair, tf32 split, fragment STS ----
        {
            float v0[8], v1[8];
            #pragma unroll
            for (int it = 0; it < 8; it++) {
                int item = it * 256 + tid;
                int r = item & 7, tm = (item >> 3) & 7, c = item >> 6;
                const float* p = inb + (size_t)(ch * 32 + c) * Tt + tm * 16 + r;
                v0[it] = p[0];
                v1[it] = p[8];
            }
            #pragma unroll
            for (int it = 0; it < 8; it++) {
                int item = it * 256 + tid;
                int r = item & 7, tm = (item >> 3) & 7, c = item >> 6;
                int k8 = c & 7, ksl = c >> 3, kp = k8 & 3, sl = (r + 2 * kp) & 7;
                float h0 = tf32_hi(v0[it]), l0 = tf32_hi(v0[it] - h0);
                float h1 = tf32_hi(v1[it]), l1 = tf32_hi(v1[it] - h1);
                fragA[((ksl * 8 + k8) * 8 + tm) * 8 + sl] = make_float4(h0, h1, l0, l1);
            }
        }
        if (ch < 15) CP_WAIT1(); else CP_WAIT0();
        __syncthreads();
        const float4* B4 = (ch & 1) ? smB1 : smB0;
        #pragma unroll
        for (int ksl = 0; ksl < 4; ksl++) {
            float4 aA[4], aB[4];
            #pragma unroll
            for (int mt = 0; mt < 4; mt++) {
                int tmg = wm * 4 + mt;
                aA[mt] = fragA[((ksl * 8 + kq) * 8 + tmg) * 8 + S];
                aB[mt] = fragA[((ksl * 8 + kq + 4) * 8 + tmg) * 8 + S];
            }
            #pragma unroll
            for (int nt = 0; nt < 8; nt++) {
                float4 bf = B4[((ksl * 4 + kq) * 32 + wn * 8 + nt) * 8 + S];
                uint32_t bh0 = __float_as_uint(bf.x), bh1 = __float_as_uint(bf.y);
                uint32_t bl0 = __float_as_uint(bf.z), bl1 = __float_as_uint(bf.w);
                #pragma unroll
                for (int mt = 0; mt < 4; mt++) {
                    uint32_t ah0 = __float_as_uint(aA[mt].x), ah1 = __float_as_uint(aA[mt].y);
                    uint32_t ah2 = __float_as_uint(aB[mt].x), ah3 = __float_as_uint(aB[mt].y);
                    uint32_t al0 = __float_as_uint(aA[mt].z), al1 = __float_as_uint(aA[mt].w);
                    uint32_t al2 = __float_as_uint(aB[mt].z), al3 = __float_as_uint(aB[mt].w);
                    mma1688(acc[mt][nt], ah0, ah1, ah2, ah3, bh0, bh1);
                    mma1688(acc[mt][nt], ah0, ah1, ah2, ah3, bl0, bl1);
                    mma1688(acc[mt][nt], al0, al1, al2, al3, bh0, bh1);
                }
            }
        }
        __syncthreads();
        if (ch + 2 < 16) ISSUE_W(ch + 2);
    }

    // ---- epilogue: bias, x fragments (k_dist A layout), ||x||^2 ----
    int g = (n0 >> 6) + wm;                       // 64-token group per wm
    float4* xf4 = (float4*)g_xf + (size_t)g * 8192;
    float xnq[4], xnq8[4];
    #pragma unroll
    for (int mt = 0; mt < 4; mt++) { xnq[mt] = 0.f; xnq8[mt] = 0.f; }

    #pragma unroll
    for (int mt = 0; mt < 4; mt++) {
        #pragma unroll
        for (int nt = 0; nt < 8; nt++) {
            int e = wn * 64 + nt * 8 + 2 * kq;
            float x0 = acc[mt][nt][0] + sBias[e];
            float x1 = acc[mt][nt][1] + sBias[e + 1];
            float x2 = acc[mt][nt][2] + sBias[e];
            float x3 = acc[mt][nt][3] + sBias[e + 1];
            xnq[mt]  += x0 * x0 + x1 * x1;
            xnq8[mt] += x2 * x2 + x3 * x3;
            {
                int k8 = e & 7, ks = e >> 3, kp = k8 & 3, sl = (q + 2 * kp) & 7;
                float h0 = tf32_hi(x0), h2 = tf32_hi(x2);
                xf4[((ks * 8 + k8) * 4 + mt) * 8 + sl] =
                    make_float4(h0, h2, tf32_hi(x0 - h0), tf32_hi(x2 - h2));
            }
            {
                int e1 = e + 1;
                int k8 = e1 & 7, ks = e1 >> 3, kp = k8 & 3, sl = (q + 2 * kp) & 7;
                float h1 = tf32_hi(x1), h3 = tf32_hi(x3);
                xf4[((ks * 8 + k8) * 4 + mt) * 8 + sl] =
                    make_float4(h1, h3, tf32_hi(x1 - h1), tf32_hi(x3 - h3));
            }
        }
    }
    #pragma unroll
    for (int mt = 0; mt < 4; mt++) {
        float a = xnq[mt], b2 = xnq8[mt];
        a  += __shfl_xor_sync(0xffffffffu, a, 1);
        a  += __shfl_xor_sync(0xffffffffu, a, 2);
        b2 += __shfl_xor_sync(0xffffffffu, b2, 1);
        b2 += __shfl_xor_sync(0xffffffffu, b2, 2);
        if (kq == 0) {
            int tl = wm * 64 + mt * 16 + q;
            atomicAdd(&sXn[tl], a);
            atomicAdd(&sXn[tl + 8], b2);
        }
    }
    __syncthreads();
    if (tid < 128) g_xn[n0 + tid] = sXn[tid];
}

// ---------------------------------------------------------------
// distance via mma.sync tf32x3: CTA = 64 tokens x all 1024 codes
// 256 threads = 8 warps (2m x 4n); warp tile 32 tokens x 32 codes
// A resident (128KB), B 3-stage cp.async (3x32KB), ONE bar/chunk
// split accumulators (hh / hl / lh) to break MMA RAW chains
// ---------------------------------------------------------------
#define DIST_DYN (131072 + 3 * 32768)
__global__ void __launch_bounds__(256, 1)
k_dist() {
    extern __shared__ char dyn[];
    float4* smA = (float4*)dyn;                         // 8192 f4
    __shared__ float redv[64][4];
    __shared__ int   redi[64][4];
    __shared__ float lred[2];

    int tid  = threadIdx.x;
    int wid  = tid >> 5, lane = tid & 31;
    int wm   = wid >> 2, wn = wid & 3;
    int q    = lane >> 2, kq = lane & 3;
    int slot = (q + 2 * kq) & 7;
    int g    = blockIdx.x;                              // token group (64 tokens)
    uint32_t smAu = smem_u32(smA);
    uint32_t smBu = smAu + 131072;

    {
        const char* src = (const char*)((const float4*)g_xf + (size_t)g * 8192);
        for (int i = tid; i < 8192; i += 256)
            cp16(smAu + (uint32_t)i * 16, src + (size_t)i * 16);
        CP_COMMIT();
    }

    #define ISSUE(gc) do {                                                        \
        int _cg = (gc) >> 3, _ch = (gc) & 7;                                      \
        const char* _s = (const char*)((const float4*)g_ef +                      \
                          (size_t)_cg * 16384 + (size_t)_ch * 2048);              \
        uint32_t _d = smBu + (uint32_t)((gc) % 3) * 32768;                        \
        for (int i = tid; i < 2048; i += 256)                                     \
            cp16(_d + (uint32_t)i * 16, _s + (size_t)i * 16);                     \
        CP_COMMIT();                                                              \
    } while (0)

    ISSUE(0);
    ISSUE(1);

    float accH[2][4][4], accM[2][4][4], accL[2][4][4];
    #pragma unroll
    for (int a = 0; a < 2; a++)
        #pragma unroll
        for (int b = 0; b < 4; b++)
            #pragma unroll
            for (int c = 0; c < 4; c++) {
                accH[a][b][c] = 0.f; accM[a][b][c] = 0.f; accL[a][b][c] = 0.f;
            }
    float bestv[4]; int besti[4];
    #pragma unroll
    for (int s = 0; s < 4; s++) { bestv[s] = 3.0e38f; besti[s] = 0; }

    for (int gc = 0; gc < 64; gc++) {
        if (gc + 1 < 64) CP_WAIT1(); else CP_WAIT0();
        __syncthreads();                 // publishes buf[gc], retires buf[gc-1] reads
        if (gc + 2 < 64) ISSUE(gc + 2);
        const float4* B4 = (const float4*)(dyn + 131072 + (gc % 3) * 32768);
        int ch = gc & 7;
        #pragma unroll
        for (int ksl = 0; ksl < 4; ksl++) {
            int ks = ch * 4 + ksl;
            float4 aA[2], aB[2];
            #pragma unroll
            for (int tm2 = 0; tm2 < 2; tm2++) {
                int tmg = wm * 2 + tm2;
                aA[tm2] = smA[(ks * 8 + kq) * 32 + tmg * 8 + slot];
                aB[tm2] = smA[(ks * 8 + kq + 4) * 32 + tmg * 8 + slot];
            }
            float4 bf[4];
            #pragma unroll
            for (int tn4 = 0; tn4 < 4; tn4++) {
                int tng = wn * 4 + tn4;
                bf[tn4] = B4[((ksl * 4 + kq) * 16 + tng) * 8 + slot];
            }
            #pragma unroll
            for (int tm2 = 0; tm2 < 2; tm2++) {
                uint32_t ah0 = __float_as_uint(aA[tm2].x), ah1 = __float_as_uint(aA[tm2].y);
                uint32_t ah2 = __float_as_uint(aB[tm2].x), ah3 = __float_as_uint(aB[tm2].y);
                uint32_t al0 = __float_as_uint(aA[tm2].z), al1 = __float_as_uint(aA[tm2].w);
                uint32_t al2 = __float_as_uint(aB[tm2].z), al3 = __float_as_uint(aB[tm2].w);
                #pragma unroll
                for (int tn4 = 0; tn4 < 4; tn4++) {
                    uint32_t bh0 = __float_as_uint(bf[tn4].x), bh1 = __float_as_uint(bf[tn4].y);
                    uint32_t bl0 = __float_as_uint(bf[tn4].z), bl1 = __float_as_uint(bf[tn4].w);
                    mma1688(accH[tm2][tn4], ah0, ah1, ah2, ah3, bh0, bh1);
                    mma1688(accM[tm2][tn4], ah0, ah1, ah2, ah3, bl0, bl1);
                    mma1688(accL[tm2][tn4], al0, al1, al2, al3, bh0, bh1);
                }
            }
        }
        if ((gc & 7) == 7) {
            int cg = gc >> 3;
            #pragma unroll
            for (int tm2 = 0; tm2 < 2; tm2++) {
                #pragma unroll
                for (int tn4 = 0; tn4 < 4; tn4++) {
                    int nb = cg * 128 + wn * 32 + tn4 * 8 + 2 * kq;
                    float e0v = __ldg(&g_enorm[nb]);
                    float e1v = __ldg(&g_enorm[nb + 1]);
                    float d00 = accH[tm2][tn4][0] + accM[tm2][tn4][0] + accL[tm2][tn4][0];
                    float d01 = accH[tm2][tn4][1] + accM[tm2][tn4][1] + accL[tm2][tn4][1];
                    float d10 = accH[tm2][tn4][2] + accM[tm2][tn4][2] + accL[tm2][tn4][2];
                    float d11 = accH[tm2][tn4][3] + accM[tm2][tn4][3] + accL[tm2][tn4][3];
                    float s00 = fmaf(-2.0f, d00, e0v);
                    float s01 = fmaf(-2.0f, d01, e1v);
                    float s10 = fmaf(-2.0f, d10, e0v);
                    float s11 = fmaf(-2.0f, d11, e1v);
                    int s0 = tm2 * 2, s1 = tm2 * 2 + 1;
                    if (s00 < bestv[s0]) { bestv[s0] = s00; besti[s0] = nb; }
                    if (s01 < bestv[s0]) { bestv[s0] = s01; besti[s0] = nb + 1; }
                    if (s10 < bestv[s1]) { bestv[s1] = s10; besti[s1] = nb; }
                    if (s11 < bestv[s1]) { bestv[s1] = s11; besti[s1] = nb + 1; }
                    #pragma unroll
                    for (int c = 0; c < 4; c++) {
                        accH[tm2][tn4][c] = 0.f;
                        accM[tm2][tn4][c] = 0.f;
                        accL[tm2][tn4][c] = 0.f;
                    }
                }
            }
        }
    }
    #pragma unroll
    for (int s = 0; s < 4; s++) {
        float v = bestv[s]; int bi = besti[s];
        #pragma unroll
        for (int off = 1; off <= 2; off <<= 1) {
            float ov = __shfl_xor_sync(0xffffffffu, v, off);
            int   oi = __shfl_xor_sync(0xffffffffu, bi, off);
            if (ov < v || (ov == v && oi < bi)) { v = ov; bi = oi; }
        }
        if ((lane & 3) == 0) {
            int row = wm * 32 + (s >> 1) * 16 + (s & 1) * 8 + q;
            redv[row][wn] = v;
            redi[row][wn] = bi;
        }
    }
    __syncthreads();
    float myd2 = 0.f;
    if (tid < 64) {
        float v = redv[tid][0]; int bi = redi[tid][0];
        #pragma unroll
        for (int j = 1; j < 4; j++) {
            float ov = redv[tid][j]; int oi = redi[tid][j];
            if (ov < v || (ov == v && oi < bi)) { v = ov; bi = oi; }
        }
        int n = g * 64 + tid;
        g_idx[n] = bi;
        atomicAdd(&g_hist[bi], 1);
        myd2 = g_xn[n] + v;                    // ||x||^2 + (||e||^2 - 2x.e)
    }
    for (int o = 16; o > 0; o >>= 1) myd2 += __shfl_down_sync(0xffffffffu, myd2, o);
    if ((tid & 31) == 0 && wid < 2) lred[wid] = myd2;
    __syncthreads();
    if (tid == 0) atomicAdd(&g_mse, (double)(lred[0] + lred[1]));
}

// ---------------------------------------------------------------
// output: z_q_out[b,e,t] = embed[q_idx[b*T+t]][e]  (32x32 transpose)
// ---------------------------------------------------------------
__global__ void k_out(const float* __restrict__ embed, float* __restrict__ out) {
    __shared__ int   qs[32];
    __shared__ float sm[32][33];
    int b  = blockIdx.z;
    int e0 = blockIdx.y * 32;
    int t0 = blockIdx.x * 32;
    int tid = threadIdx.x;
    if (tid < 32) qs[tid] = g_idx[b * Tt + t0 + tid];
    __syncthreads();
    {
        int j = tid >> 3, gg = tid & 7;
        const float4* erow = (const float4*)(embed + (size_t)qs[j] * Ee + e0);
        float4 v = erow[gg];
        sm[j][gg * 4 + 0] = v.x; sm[j][gg * 4 + 1] = v.y;
        sm[j][gg * 4 + 2] = v.z; sm[j][gg * 4 + 3] = v.w;
    }
    __syncthreads();
    int tl = tid & 31, eb = tid >> 5;
    #pragma unroll
    for (int r = 0; r < 4; r++) {
        int el = eb + r * 8;
        out[((size_t)b * Ee + e0 + el) * Tt + t0 + tl] = sm[tl][el];
    }
}

// ---------------------------------------------------------------
// tail scalars
// ---------------------------------------------------------------
__global__ void k_tail(float* __restrict__ out) {
    __shared__ float red[32];
    int tid = threadIdx.x;                     // 1024
    float p = (float)g_hist[tid] / 65536.0f;
    float term = -p * logf(p + 1e-10f);
    for (int o = 16; o > 0; o >>= 1) term += __shfl_down_sync(0xffffffffu, term, o);
    if ((tid & 31) == 0) red[tid >> 5] = term;
    __syncthreads();
    const size_t base = (size_t)Bb * Ee * Tt;
    if (tid == 0) {
        float lp = 0.f;
        #pragma unroll
        for (int i = 0; i < 32; i++) lp += red[i];
        out[base + 0]  = (float)(1.25 * (g_mse / (double)((size_t)NTOK * Ee)));
        out[base + 17] = lp;
    }
    if (tid < 16) out[base + 1 + tid] = (float)(log(1024.0) * 4096.0);
}

// ---------------------------------------------------------------
extern "C" void kernel_launch(void* const* d_in, const int* in_sizes, int n_in,
                              void* d_out, int out_size) {
    const float* inputs = (const float*)d_in[0];   // [16, 512, 4096]
    const float* proj_w = (const float*)d_in[1];   // [256, 512]
    const float* proj_b = (const float*)d_in[2];   // [256]
    const float* embed  = (const float*)d_in[3];   // [1024, 256]
    float* out = (float*)d_out;

    cudaFuncSetAttribute(k_proj, cudaFuncAttributeMaxDynamicSharedMemorySize, PROJ_DYN);
    cudaFuncSetAttribute(k_dist, cudaFuncAttributeMaxDynamicSharedMemorySize, DIST_DYN);

    k_init<<<NE, 256>>>(embed);
    k_winit<<<Cc, 256>>>(proj_w);
    k_proj<<<NTOK / 128, 256, PROJ_DYN>>>(inputs, proj_b);
    k_dist<<<NTOK / 64, 256, DIST_DYN>>>();
    dim3 g3(Tt / 32, Ee / 32, Bb);
    k_out<<<g3, 256>>>(embed, out);
    k_tail<<<1, 1024>>>(out);
}

// round 9
// speedup vs baseline: 1.0608x; 1.0568x over previous
#include <cuda_runtime.h>
#include <math.h>
#include <cstdint>

#define Bb   16
#define Tt   4096
#define Cc   512
#define Ee   256
#define NE   1024
#define NTOK (Bb*Tt)

// ---- scratch (static device memory) ----
// x fragments: per 64-token group: [ks(32)][k(8)][tm(4)][slot(8)] float4
//   float4 = {hi[m], hi[m+8], lo[m], lo[m+8]} for one k(=e)
__device__ __align__(16) float g_xf[(size_t)NTOK * Ee * 2];
// embed fragments: per 128-code group: [ks(32)][kp(4)][tn(16)][slot(8)] float4
__device__ __align__(16) float g_ef[(size_t)NE * Ee * 2];
// proj-weight fragments: [ks(64)][kp(4)][tn(32)][slot(8)] float4
__device__ __align__(16) float g_wf[(size_t)Ee * Cc * 2];
__device__ float  g_enorm[NE];
__device__ float  g_xn[NTOK];       // per-token ||x||^2
__device__ int    g_idx[NTOK];
__device__ int    g_hist[NE];
__device__ double g_mse;            // sum of d2_min over tokens

// ---------------- helpers ----------------
__device__ __forceinline__ uint32_t smem_u32(const void* p) {
    uint32_t a;
    asm("{ .reg .u64 t; cvta.to.shared.u64 t, %1; cvt.u32.u64 %0, t; }" : "=r"(a) : "l"(p));
    return a;
}
__device__ __forceinline__ float tf32_hi(float x) {
    uint32_t b; asm("cvt.rna.tf32.f32 %0, %1;" : "=r"(b) : "f"(x));
    return __uint_as_float(b);
}
__device__ __forceinline__ void mma1688(float* d, uint32_t a0, uint32_t a1,
                                        uint32_t a2, uint32_t a3,
                                        uint32_t b0, uint32_t b1) {
    asm volatile(
        "mma.sync.aligned.m16n8k8.row.col.f32.tf32.tf32.f32 "
        "{%0,%1,%2,%3}, {%4,%5,%6,%7}, {%8,%9}, {%0,%1,%2,%3};"
        : "+f"(d[0]), "+f"(d[1]), "+f"(d[2]), "+f"(d[3])
        : "r"(a0), "r"(a1), "r"(a2), "r"(a3), "r"(b0), "r"(b1));
}
__device__ __forceinline__ void cp16(uint32_t s, const void* g) {
    asm volatile("cp.async.cg.shared.global [%0], [%1], 16;" :: "r"(s), "l"(g));
}
#define CP_COMMIT() asm volatile("cp.async.commit_group;" ::: "memory")
#define CP_WAIT1()  asm volatile("cp.async.wait_group 1;" ::: "memory")
#define CP_WAIT0()  asm volatile("cp.async.wait_group 0;" ::: "memory")

// ---------------------------------------------------------------
// init: ||e||^2, embed hi/lo fragment layout, zero hist/mse
// ---------------------------------------------------------------
__global__ void k_init(const float* __restrict__ embed) {
    int c = blockIdx.x;                 // 1024 blocks, 256 threads
    int e = threadIdx.x;
    float v = embed[(size_t)c * Ee + e];
    float h = tf32_hi(v);
    float l = tf32_hi(v - h);
    int cg = c >> 7, cl = c & 127, tn = cl >> 3, n8 = cl & 7;
    int ks = e >> 3, k8 = e & 7, kp = k8 & 3, half = k8 >> 2;
    int slot = (n8 + 2 * kp) & 7;
    size_t i4 = ((((size_t)cg * 32 + ks) * 4 + kp) * 16 + tn) * 8 + slot;
    g_ef[i4 * 4 + half]     = h;
    g_ef[i4 * 4 + 2 + half] = l;

    float s = v * v;
    __shared__ float red[8];
    for (int o = 16; o > 0; o >>= 1) s += __shfl_down_sync(0xffffffffu, s, o);
    if ((e & 31) == 0) red[e >> 5] = s;
    __syncthreads();
    if (e == 0) {
        float t = 0.f;
        #pragma unroll
        for (int i = 0; i < 8; i++) t += red[i];
        g_enorm[c] = t;
        g_hist[c]  = 0;
        if (c == 0) g_mse = 0.0;
    }
}

// ---------------------------------------------------------------
// winit: proj weight hi/lo fragments (B operand layout)
// ---------------------------------------------------------------
__global__ void k_winit(const float* __restrict__ w) {
    int c = blockIdx.x;                 // 0..511
    int e = threadIdx.x;                // 0..255
    float v = w[(size_t)e * Cc + c];
    float h = tf32_hi(v);
    float l = tf32_hi(v - h);
    int ks = c >> 3, k8 = c & 7, kp = k8 & 3, half = k8 >> 2;
    int tn = e >> 3, n8 = e & 7;
    int slot = (n8 + 2 * kp) & 7;
    size_t i4 = (((size_t)ks * 4 + kp) * 32 + tn) * 8 + slot;
    g_wf[i4 * 4 + half]     = h;
    g_wf[i4 * 4 + 2 + half] = l;
}

// ---------------------------------------------------------------
// projection via mma.sync tf32x3: CTA = 128 tokens x 256 feats
// 256 threads = 8 warps (2m x 4n); warp tile 64 tokens x 64 feats
// ---------------------------------------------------------------
#define PROJ_DYN (32768 + 2 * 65536)
__global__ void __launch_bounds__(256, 1)
k_proj(const float* __restrict__ in, const float* __restrict__ bias) {
    extern __shared__ char dyn[];
    float4* fragA = (float4*)dyn;                                   // 2048 f4
    float4* smB0  = (float4*)(dyn + 32768);                         // 4096 f4
    float4* smB1  = (float4*)(dyn + 98304);                         // 4096 f4
    __shared__ float sBias[256];
    __shared__ float sXn[128];

    int tid  = threadIdx.x;
    int lane = tid & 31, wid = tid >> 5;
    int wm   = wid >> 2, wn = wid & 3;
    int q    = lane >> 2, kq = lane & 3;
    int S    = (q + 2 * kq) & 7;
    int n0   = blockIdx.x * 128;
    int b    = n0 >> 12, t0 = n0 & 4095;
    const float* inb = in + (size_t)b * Cc * Tt + t0;
    uint32_t smBu[2] = { smem_u32(smB0), smem_u32(smB1) };

    sBias[tid] = bias[tid];
    if (tid < 128) sXn[tid] = 0.f;

    #define ISSUE_W(ch) do {                                                     \
        const char* _s = (const char*)((const float4*)g_wf + (size_t)(ch)*4096); \
        uint32_t _d = smBu[(ch) & 1];                                            \
        for (int i = tid; i < 4096; i += 256)                                    \
            cp16(_d + (uint32_t)i * 16, _s + (size_t)i * 16);                    \
        CP_COMMIT();                                                             \
    } while (0)

    ISSUE_W(0);
    ISSUE_W(1);

    float acc[4][8][4];
    #pragma unroll
    for (int a = 0; a < 4; a++)
        #pragma unroll
        for (int bb = 0; bb < 8; bb++)
            #pragma unroll
            for (int cix = 0; cix < 4; cix++) acc[a][bb][cix] = 0.f;

    for (int ch = 0; ch < 16; ch++) {
        // ---- A fill: LDG token pair, tf32 split, fragment STS ----
        {
            float v0[8], v1[8];
            #pragma unroll
            for (int it = 0; it < 8; it++) {
                int item = it * 256 + tid;
                int r = item & 7, tm = (item >> 3) & 7, c = item >> 6;
                const float* p = inb + (size_t)(ch * 32 + c) * Tt + tm * 16 + r;
                v0[it] = p[0];
                v1[it] = p[8];
            }
            #pragma unroll
            for (int it = 0; it < 8; it++) {
                int item = it * 256 + tid;
                int r = item & 7, tm = (item >> 3) & 7, c = item >> 6;
                int k8 = c & 7, ksl = c >> 3, kp = k8 & 3, sl = (r + 2 * kp) & 7;
                float h0 = tf32_hi(v0[it]), l0 = tf32_hi(v0[it] - h0);
                float h1 = tf32_hi(v1[it]), l1 = tf32_hi(v1[it] - h1);
                fragA[((ksl * 8 + k8) * 8 + tm) * 8 + sl] = make_float4(h0, h1, l0, l1);
            }
        }
        if (ch < 15) CP_WAIT1(); else CP_WAIT0();
        __syncthreads();
        const float4* B4 = (ch & 1) ? smB1 : smB0;
        #pragma unroll
        for (int ksl = 0; ksl < 4; ksl++) {
            float4 aA[4], aB[4];
            #pragma unroll
            for (int mt = 0; mt < 4; mt++) {
                int tmg = wm * 4 + mt;
                aA[mt] = fragA[((ksl * 8 + kq) * 8 + tmg) * 8 + S];
                aB[mt] = fragA[((ksl * 8 + kq + 4) * 8 + tmg) * 8 + S];
            }
            #pragma unroll
            for (int nt = 0; nt < 8; nt++) {
                float4 bf = B4[((ksl * 4 + kq) * 32 + wn * 8 + nt) * 8 + S];
                uint32_t bh0 = __float_as_uint(bf.x), bh1 = __float_as_uint(bf.y);
                uint32_t bl0 = __float_as_uint(bf.z), bl1 = __float_as_uint(bf.w);
                #pragma unroll
                for (int mt = 0; mt < 4; mt++) {
                    uint32_t ah0 = __float_as_uint(aA[mt].x), ah1 = __float_as_uint(aA[mt].y);
                    uint32_t ah2 = __float_as_uint(aB[mt].x), ah3 = __float_as_uint(aB[mt].y);
                    uint32_t al0 = __float_as_uint(aA[mt].z), al1 = __float_as_uint(aA[mt].w);
                    uint32_t al2 = __float_as_uint(aB[mt].z), al3 = __float_as_uint(aB[mt].w);
                    mma1688(acc[mt][nt], ah0, ah1, ah2, ah3, bh0, bh1);
                    mma1688(acc[mt][nt], ah0, ah1, ah2, ah3, bl0, bl1);
                    mma1688(acc[mt][nt], al0, al1, al2, al3, bh0, bh1);
                }
            }
        }
        __syncthreads();
        if (ch + 2 < 16) ISSUE_W(ch + 2);
    }

    // ---- epilogue: bias, x fragments (k_dist A layout), ||x||^2 ----
    int g = (n0 >> 6) + wm;                       // 64-token group per wm
    float4* xf4 = (float4*)g_xf + (size_t)g * 8192;
    float xnq[4], xnq8[4];
    #pragma unroll
    for (int mt = 0; mt < 4; mt++) { xnq[mt] = 0.f; xnq8[mt] = 0.f; }

    #pragma unroll
    for (int mt = 0; mt < 4; mt++) {
        #pragma unroll
        for (int nt = 0; nt < 8; nt++) {
            int e = wn * 64 + nt * 8 + 2 * kq;
            float x0 = acc[mt][nt][0] + sBias[e];
            float x1 = acc[mt][nt][1] + sBias[e + 1];
            float x2 = acc[mt][nt][2] + sBias[e];
            float x3 = acc[mt][nt][3] + sBias[e + 1];
            xnq[mt]  += x0 * x0 + x1 * x1;
            xnq8[mt] += x2 * x2 + x3 * x3;
            {
                int k8 = e & 7, ks = e >> 3, kp = k8 & 3, sl = (q + 2 * kp) & 7;
                float h0 = tf32_hi(x0), h2 = tf32_hi(x2);
                xf4[((ks * 8 + k8) * 4 + mt) * 8 + sl] =
                    make_float4(h0, h2, tf32_hi(x0 - h0), tf32_hi(x2 - h2));
            }
            {
                int e1 = e + 1;
                int k8 = e1 & 7, ks = e1 >> 3, kp = k8 & 3, sl = (q + 2 * kp) & 7;
                float h1 = tf32_hi(x1), h3 = tf32_hi(x3);
                xf4[((ks * 8 + k8) * 4 + mt) * 8 + sl] =
                    make_float4(h1, h3, tf32_hi(x1 - h1), tf32_hi(x3 - h3));
            }
        }
    }
    #pragma unroll
    for (int mt = 0; mt < 4; mt++) {
        float a = xnq[mt], b2 = xnq8[mt];
        a  += __shfl_xor_sync(0xffffffffu, a, 1);
        a  += __shfl_xor_sync(0xffffffffu, a, 2);
        b2 += __shfl_xor_sync(0xffffffffu, b2, 1);
        b2 += __shfl_xor_sync(0xffffffffu, b2, 2);
        if (kq == 0) {
            int tl = wm * 64 + mt * 16 + q;
            atomicAdd(&sXn[tl], a);
            atomicAdd(&sXn[tl + 8], b2);
        }
    }
    __syncthreads();
    if (tid < 128) g_xn[n0 + tid] = sXn[tid];
}

// ---------------------------------------------------------------
// distance via mma.sync tf32x3: CTA = 64 tokens x all 1024 codes
// 256 threads = 8 warps (2m x 4n); warp tile 32 tokens x 64 CODES
// chunk = 256 codes x 16 k (32KB), 3-stage ring, one bar/chunk
// A resident (128KB); 128 B of smem per MMA (was 170)
// ---------------------------------------------------------------
#define DIST_DYN (131072 + 3 * 32768)
__global__ void __launch_bounds__(256, 1)
k_dist() {
    extern __shared__ char dyn[];
    float4* smA = (float4*)dyn;                         // 8192 f4

    int tid  = threadIdx.x;
    int wid  = tid >> 5, lane = tid & 31;
    int wm   = wid >> 2, wn = wid & 3;
    int cgh  = wn >> 1, wn1 = wn & 1;
    int q    = lane >> 2, kq = lane & 3;
    int slot = (q + 2 * kq) & 7;
    int g    = blockIdx.x;                              // token group (64 tokens)
    uint32_t smAu = smem_u32(dyn);
    uint32_t smBu = smAu + 131072;

    // A fill (group 0)
    {
        const char* src = (const char*)((const float4*)g_xf + (size_t)g * 8192);
        for (int i = tid; i < 8192; i += 256)
            cp16(smAu + (uint32_t)i * 16, src + (size_t)i * 16);
        CP_COMMIT();
    }

    // chunk cc: cgp = cc>>4 (256-code group), kc = cc&15 (k16 chunk)
    // smB layout: [cgHalf(2)][ksl(2)][kp(4)][tn(16)][slot(8)] float4
    #define ISSUE(cc) do {                                                        \
        int _cgp = (cc) >> 4, _kc = (cc) & 15;                                    \
        uint32_t _d = smBu + (uint32_t)((cc) % 3) * 32768;                        \
        const char* _s0 = (const char*)((const float4*)g_ef +                     \
                           ((size_t)(_cgp * 2) * 32 + _kc * 2) * 512);            \
        const char* _s1 = (const char*)((const float4*)g_ef +                     \
                           ((size_t)(_cgp * 2 + 1) * 32 + _kc * 2) * 512);        \
        for (int i = tid; i < 1024; i += 256) {                                   \
            cp16(_d + (uint32_t)i * 16, _s0 + (size_t)i * 16);                    \
            cp16(_d + 16384 + (uint32_t)i * 16, _s1 + (size_t)i * 16);            \
        }                                                                         \
        CP_COMMIT();                                                              \
    } while (0)

    ISSUE(0);
    ISSUE(1);

    float acc[2][8][4];
    #pragma unroll
    for (int a = 0; a < 2; a++)
        #pragma unroll
        for (int b = 0; b < 8; b++)
            #pragma unroll
            for (int c = 0; c < 4; c++) acc[a][b][c] = 0.f;
    float bestv[4]; int besti[4];
    #pragma unroll
    for (int s = 0; s < 4; s++) { bestv[s] = 3.0e38f; besti[s] = 0; }

    for (int cc = 0; cc < 64; cc++) {
        if (cc + 1 < 64) CP_WAIT1(); else CP_WAIT0();
        __syncthreads();                 // publishes buf[cc]; retires reads of buf[cc-1]
        if (cc + 2 < 64) ISSUE(cc + 2);
        const float4* B4 = (const float4*)(dyn + 131072 + (cc % 3) * 32768);
        int kc = cc & 15;
        #pragma unroll
        for (int ksl = 0; ksl < 2; ksl++) {
            int ks = kc * 2 + ksl;
            float4 aA[2], aB[2];
            #pragma unroll
            for (int tm2 = 0; tm2 < 2; tm2++) {
                int tmg = wm * 2 + tm2;
                aA[tm2] = smA[(ks * 8 + kq) * 32 + tmg * 8 + slot];
                aB[tm2] = smA[(ks * 8 + kq + 4) * 32 + tmg * 8 + slot];
            }
            uint32_t ah0[2], ah1[2], ah2[2], ah3[2], al0[2], al1[2], al2[2], al3[2];
            #pragma unroll
            for (int tm2 = 0; tm2 < 2; tm2++) {
                ah0[tm2] = __float_as_uint(aA[tm2].x); ah1[tm2] = __float_as_uint(aA[tm2].y);
                ah2[tm2] = __float_as_uint(aB[tm2].x); ah3[tm2] = __float_as_uint(aB[tm2].y);
                al0[tm2] = __float_as_uint(aA[tm2].z); al1[tm2] = __float_as_uint(aA[tm2].w);
                al2[tm2] = __float_as_uint(aB[tm2].z); al3[tm2] = __float_as_uint(aB[tm2].w);
            }
            #pragma unroll
            for (int tn = 0; tn < 8; tn++) {
                int tnl = wn1 * 8 + tn;
                float4 bf = B4[cgh * 1024 + ksl * 512 + (kq * 16 + tnl) * 8 + slot];
                uint32_t bh0 = __float_as_uint(bf.x), bh1 = __float_as_uint(bf.y);
                uint32_t bl0 = __float_as_uint(bf.z), bl1 = __float_as_uint(bf.w);
                #pragma unroll
                for (int tm2 = 0; tm2 < 2; tm2++) {
                    mma1688(acc[tm2][tn], ah0[tm2], ah1[tm2], ah2[tm2], ah3[tm2], bh0, bh1);
                    mma1688(acc[tm2][tn], ah0[tm2], ah1[tm2], ah2[tm2], ah3[tm2], bl0, bl1);
                    mma1688(acc[tm2][tn], al0[tm2], al1[tm2], al2[tm2], al3[tm2], bh0, bh1);
                }
            }
        }
        if (kc == 15) {
            int cgp = cc >> 4;
            #pragma unroll
            for (int tn = 0; tn < 8; tn++) {
                int tnl = wn1 * 8 + tn;
                int nb = cgp * 256 + cgh * 128 + tnl * 8 + 2 * kq;
                float e0v = __ldg(&g_enorm[nb]);
                float e1v = __ldg(&g_enorm[nb + 1]);
                #pragma unroll
                for (int tm2 = 0; tm2 < 2; tm2++) {
                    float s00 = fmaf(-2.0f, acc[tm2][tn][0], e0v);
                    float s01 = fmaf(-2.0f, acc[tm2][tn][1], e1v);
                    float s10 = fmaf(-2.0f, acc[tm2][tn][2], e0v);
                    float s11 = fmaf(-2.0f, acc[tm2][tn][3], e1v);
                    int s0 = tm2 * 2, s1 = tm2 * 2 + 1;
                    if (s00 < bestv[s0]) { bestv[s0] = s00; besti[s0] = nb; }
                    if (s01 < bestv[s0]) { bestv[s0] = s01; besti[s0] = nb + 1; }
                    if (s10 < bestv[s1]) { bestv[s1] = s10; besti[s1] = nb; }
                    if (s11 < bestv[s1]) { bestv[s1] = s11; besti[s1] = nb + 1; }
                    acc[tm2][tn][0] = 0.f; acc[tm2][tn][1] = 0.f;
                    acc[tm2][tn][2] = 0.f; acc[tm2][tn][3] = 0.f;
                }
            }
        }
    }
    __syncthreads();                     // all compute done; B ring dead, reuse it
    float* redv = (float*)(dyn + 131072);            // 64*4 floats
    int*   redi = (int*)(dyn + 131072 + 1024);       // 64*4 ints
    float* lred = (float*)(dyn + 131072 + 2048);     // 2 floats

    #pragma unroll
    for (int s = 0; s < 4; s++) {
        float v = bestv[s]; int bi = besti[s];
        #pragma unroll
        for (int off = 1; off <= 2; off <<= 1) {
            float ov = __shfl_xor_sync(0xffffffffu, v, off);
            int   oi = __shfl_xor_sync(0xffffffffu, bi, off);
            if (ov < v || (ov == v && oi < bi)) { v = ov; bi = oi; }
        }
        if ((lane & 3) == 0) {
            int row = wm * 32 + (s >> 1) * 16 + (s & 1) * 8 + q;
            redv[row * 4 + wn] = v;
            redi[row * 4 + wn] = bi;
        }
    }
    __syncthreads();
    float myd2 = 0.f;
    if (tid < 64) {
        float v = redv[tid * 4]; int bi = redi[tid * 4];
        #pragma unroll
        for (int j = 1; j < 4; j++) {
            float ov = redv[tid * 4 + j]; int oi = redi[tid * 4 + j];
            if (ov < v || (ov == v && oi < bi)) { v = ov; bi = oi; }
        }
        int n = g * 64 + tid;
        g_idx[n] = bi;
        atomicAdd(&g_hist[bi], 1);
        myd2 = g_xn[n] + v;                    // ||x||^2 + (||e||^2 - 2x.e)
    }
    for (int o = 16; o > 0; o >>= 1) myd2 += __shfl_down_sync(0xffffffffu, myd2, o);
    if ((tid & 31) == 0 && wid < 2) lred[wid] = myd2;
    __syncthreads();
    if (tid == 0) atomicAdd(&g_mse, (double)(lred[0] + lred[1]));
}

// ---------------------------------------------------------------
// output: z_q_out[b,e,t] = embed[q_idx[b*T+t]][e]  (32x32 transpose)
// ---------------------------------------------------------------
__global__ void k_out(const float* __restrict__ embed, float* __restrict__ out) {
    __shared__ int   qs[32];
    __shared__ float sm[32][33];
    int b  = blockIdx.z;
    int e0 = blockIdx.y * 32;
    int t0 = blockIdx.x * 32;
    int tid = threadIdx.x;
    if (tid < 32) qs[tid] = g_idx[b * Tt + t0 + tid];
    __syncthreads();
    {
        int j = tid >> 3, gg = tid & 7;
        const float4* erow = (const float4*)(embed + (size_t)qs[j] * Ee + e0);
        float4 v = erow[gg];
        sm[j][gg * 4 + 0] = v.x; sm[j][gg * 4 + 1] = v.y;
        sm[j][gg * 4 + 2] = v.z; sm[j][gg * 4 + 3] = v.w;
    }
    __syncthreads();
    int tl = tid & 31, eb = tid >> 5;
    #pragma unroll
    for (int r = 0; r < 4; r++) {
        int el = eb + r * 8;
        out[((size_t)b * Ee + e0 + el) * Tt + t0 + tl] = sm[tl][el];
    }
}

// ---------------------------------------------------------------
// tail scalars
// ---------------------------------------------------------------
__global__ void k_tail(float* __restrict__ out) {
    __shared__ float red[32];
    int tid = threadIdx.x;                     // 1024
    float p = (float)g_hist[tid] / 65536.0f;
    float term = -p * logf(p + 1e-10f);
    for (int o = 16; o > 0; o >>= 1) term += __shfl_down_sync(0xffffffffu, term, o);
    if ((tid & 31) == 0) red[tid >> 5] = term;
    __syncthreads();
    const size_t base = (size_t)Bb * Ee * Tt;
    if (tid == 0) {
        float lp = 0.f;
        #pragma unroll
        for (int i = 0; i < 32; i++) lp += red[i];
        out[base + 0]  = (float)(1.25 * (g_mse / (double)((size_t)NTOK * Ee)));
        out[base + 17] = lp;
    }
    if (tid < 16) out[base + 1 + tid] = (float)(log(1024.0) * 4096.0);
}

// ---------------------------------------------------------------
extern "C" void kernel_launch(void* const* d_in, const int* in_sizes, int n_in,
                              void* d_out, int out_size) {
    const float* inputs = (const float*)d_in[0];   // [16, 512, 4096]
    const float* proj_w = (const float*)d_in[1];   // [256, 512]
    const float* proj_b = (const float*)d_in[2];   // [256]
    const float* embed  = (const float*)d_in[3];   // [1024, 256]
    float* out = (float*)d_out;

    cudaFuncSetAttribute(k_proj, cudaFuncAttributeMaxDynamicSharedMemorySize, PROJ_DYN);
    cudaFuncSetAttribute(k_dist, cudaFuncAttributeMaxDynamicSharedMemorySize, DIST_DYN);

    k_init<<<NE, 256>>>(embed);
    k_winit<<<Cc, 256>>>(proj_w);
    k_proj<<<NTOK / 128, 256, PROJ_DYN>>>(inputs, proj_b);
    k_dist<<<NTOK / 64, 256, DIST_DYN>>>();
    dim3 g3(Tt / 32, Ee / 32, Bb);
    k_out<<<g3, 256>>>(embed, out);
    k_tail<<<1, 1024>>>(out);
}

// round 10
// speedup vs baseline: 2.2270x; 2.0994x over previous
#include <cuda_runtime.h>
#include <cuda_fp16.h>
#include <math.h>
#include <cstdint>

#define Bb   16
#define Tt   4096
#define Cc   512
#define Ee   256
#define NE   1024
#define NTOK (Bb*Tt)

// ---- scratch (static device memory) ----
// x fragments (f16 hi/lo): per 64-token group (64KB = 4096 float4):
//   [hi: (ks16*4+tm)*32+lane][lo: +2048]  float4 = {a0,a1,a2,a3} packed f16x2
__device__ __align__(16) float g_xf[(size_t)NTOK * Ee];
// embed fragments (f16): [cgp(4)][ks(16)][tn(32)][lane(32)] float4 = {b0h,b1h,b0l,b1l}
__device__ __align__(16) float g_ef[(size_t)NE * Ee];
// proj-weight fragments (f16): [ks(32)][tn(32)][lane(32)] float4
__device__ __align__(16) float g_wf[(size_t)Ee * Cc];
__device__ float  g_enorm[NE];
__device__ float  g_xn[NTOK];       // per-token ||x||^2
__device__ int    g_idx[NTOK];
__device__ int    g_hist[NE];
__device__ double g_mse;            // sum of d2_min over tokens

// ---------------- helpers ----------------
__device__ __forceinline__ uint32_t smem_u32(const void* p) {
    uint32_t a;
    asm("{ .reg .u64 t; cvta.to.shared.u64 t, %1; cvt.u32.u64 %0, t; }" : "=r"(a) : "l"(p));
    return a;
}
// split two floats into packed f16x2 hi + f16x2 lo
__device__ __forceinline__ uint32_t packsplit(float x0, float x1, uint32_t& lo) {
    __half h0 = __float2half_rn(x0);
    __half l0 = __float2half_rn(x0 - __half2float(h0));
    __half h1 = __float2half_rn(x1);
    __half l1 = __float2half_rn(x1 - __half2float(h1));
    __half2 hh = __halves2half2(h0, h1), ll = __halves2half2(l0, l1);
    lo = *(uint32_t*)&ll;
    return *(uint32_t*)&hh;
}
__device__ __forceinline__ void mmaf16(float* d, uint32_t a0, uint32_t a1,
                                       uint32_t a2, uint32_t a3,
                                       uint32_t b0, uint32_t b1) {
    asm volatile(
        "mma.sync.aligned.m16n8k16.row.col.f32.f16.f16.f32 "
        "{%0,%1,%2,%3}, {%4,%5,%6,%7}, {%8,%9}, {%0,%1,%2,%3};"
        : "+f"(d[0]), "+f"(d[1]), "+f"(d[2]), "+f"(d[3])
        : "r"(a0), "r"(a1), "r"(a2), "r"(a3), "r"(b0), "r"(b1));
}
__device__ __forceinline__ void cp16(uint32_t s, const void* g) {
    asm volatile("cp.async.cg.shared.global [%0], [%1], 16;" :: "r"(s), "l"(g));
}
#define CP_COMMIT() asm volatile("cp.async.commit_group;" ::: "memory")
#define CP_WAIT1()  asm volatile("cp.async.wait_group 1;" ::: "memory")
#define CP_WAIT0()  asm volatile("cp.async.wait_group 0;" ::: "memory")

// ---------------------------------------------------------------
// init: ||e||^2, embed f16 hi/lo fragments, zero hist/mse
// ---------------------------------------------------------------
__global__ void k_init(const float* __restrict__ embed) {
    int c = blockIdx.x;                 // code 0..1023
    int e = threadIdx.x;                // k 0..255
    float v = embed[(size_t)c * Ee + e];
    __half h = __float2half_rn(v);
    __half l = __float2half_rn(v - __half2float(h));
    int cgp = c >> 8, cl = c & 255, tn = cl >> 3, qq = cl & 7;
    int ks = e >> 4, r = e & 15, kq = (r >> 1) & 3, odd = r & 1, b1f = r >> 3;
    int lane = qq * 4 + kq;
    size_t f4 = (((size_t)cgp * 16 + ks) * 32 + tn) * 32 + lane;
    __half* hp = (__half*)g_ef;
    hp[f4 * 8 + b1f * 2 + odd]     = h;
    hp[f4 * 8 + 4 + b1f * 2 + odd] = l;

    float s = v * v;
    __shared__ float red[8];
    for (int o = 16; o > 0; o >>= 1) s += __shfl_down_sync(0xffffffffu, s, o);
    if ((e & 31) == 0) red[e >> 5] = s;
    __syncthreads();
    if (e == 0) {
        float t = 0.f;
        #pragma unroll
        for (int i = 0; i < 8; i++) t += red[i];
        g_enorm[c] = t;
        g_hist[c]  = 0;
        if (c == 0) g_mse = 0.0;
    }
}

// ---------------------------------------------------------------
// winit: proj weight f16 hi/lo fragments (B operand layout)
// ---------------------------------------------------------------
__global__ void k_winit(const float* __restrict__ w) {
    int c = blockIdx.x;                 // 0..511 (k dim)
    int e = threadIdx.x;                // 0..255 (n dim)
    float v = w[(size_t)e * Cc + c];
    __half h = __float2half_rn(v);
    __half l = __float2half_rn(v - __half2float(h));
    int ks = c >> 4, r = c & 15, kq = (r >> 1) & 3, odd = r & 1, b1f = r >> 3;
    int tn = e >> 3, qq = e & 7;
    int lane = qq * 4 + kq;
    size_t f4 = ((size_t)ks * 32 + tn) * 32 + lane;
    __half* hp = (__half*)g_wf;
    hp[f4 * 8 + b1f * 2 + odd]     = h;
    hp[f4 * 8 + 4 + b1f * 2 + odd] = l;
}

// ---------------------------------------------------------------
// projection via mma.sync f16x3 (m16n8k16): CTA = 128 tokens x 256 feats
// 256 threads = 8 warps (2m x 4n); warp tile 64 tokens x 64 feats
// ---------------------------------------------------------------
#define PROJ_DYN (16384 + 2 * 32768)
__global__ void __launch_bounds__(256, 1)
k_proj(const float* __restrict__ in, const float* __restrict__ bias) {
    extern __shared__ char dyn[];
    float4* fragA = (float4*)dyn;                    // 1024 f4: hi[0,512), lo[512,1024)
    float4* smW0  = (float4*)(dyn + 16384);          // 2048 f4
    float4* smW1  = (float4*)(dyn + 49152);          // 2048 f4
    __shared__ float sBias[256];
    __shared__ float sXn[128];

    int tid  = threadIdx.x;
    int lane = tid & 31, wid = tid >> 5;
    int wm   = wid >> 2, wn = wid & 3;
    int q    = lane >> 2, kq = lane & 3;
    int n0   = blockIdx.x * 128;
    int b    = n0 >> 12, t0 = n0 & 4095;
    const float* inb = in + (size_t)b * Cc * Tt + t0;
    uint32_t smWu[2] = { smem_u32(smW0), smem_u32(smW1) };

    sBias[tid] = bias[tid];
    if (tid < 128) sXn[tid] = 0.f;

    #define ISSUE_W(ch) do {                                                      \
        const char* _s = (const char*)((const float4*)g_wf + (size_t)(ch)*2048);  \
        uint32_t _d = smWu[(ch) & 1];                                             \
        for (int i = tid; i < 2048; i += 256)                                     \
            cp16(_d + (uint32_t)i * 16, _s + (size_t)i * 16);                     \
        CP_COMMIT();                                                              \
    } while (0)

    ISSUE_W(0);
    ISSUE_W(1);

    float acc[4][8][4];
    #pragma unroll
    for (int a = 0; a < 4; a++)
        #pragma unroll
        for (int bb = 0; bb < 8; bb++)
            #pragma unroll
            for (int cix = 0; cix < 4; cix++) acc[a][bb][cix] = 0.f;

    for (int ch = 0; ch < 16; ch++) {
        // ---- A fill: LDG 8 values per set, f16-split, STS.128 hi+lo ----
        #pragma unroll
        for (int it = 0; it < 2; it++) {
            int item = it * 256 + tid;                  // 0..511
            int akq = item & 3, aq = (item >> 2) & 7;
            int tm = (item >> 5) & 7, ksl = item >> 8;
            const float* p = inb + (size_t)(ch * 32 + ksl * 16 + 2 * akq) * Tt
                               + tm * 16 + aq;
            float r0k0 = p[0],        r8k0 = p[8];
            float r0k1 = p[Tt],       r8k1 = p[Tt + 8];
            float r0k8 = p[8 * Tt],   r8k8 = p[8 * Tt + 8];
            float r0k9 = p[9 * Tt],   r8k9 = p[9 * Tt + 8];
            uint32_t l0, l1, l2, l3;
            uint32_t h0 = packsplit(r0k0, r0k1, l0);
            uint32_t h1 = packsplit(r8k0, r8k1, l1);
            uint32_t h2 = packsplit(r0k8, r0k9, l2);
            uint32_t h3 = packsplit(r8k8, r8k9, l3);
            int sl = (ksl * 8 + tm) * 32 + aq * 4 + akq;
            fragA[sl]       = make_float4(__uint_as_float(h0), __uint_as_float(h1),
                                          __uint_as_float(h2), __uint_as_float(h3));
            fragA[512 + sl] = make_float4(__uint_as_float(l0), __uint_as_float(l1),
                                          __uint_as_float(l2), __uint_as_float(l3));
        }
        if (ch < 15) CP_WAIT1(); else CP_WAIT0();
        __syncthreads();
        const float4* W4 = (ch & 1) ? smW1 : smW0;
        #pragma unroll
        for (int ksl = 0; ksl < 2; ksl++) {
            uint32_t aH[4][4], aL[4][4];
            #pragma unroll
            for (int mt = 0; mt < 4; mt++) {
                int tmg = wm * 4 + mt;
                float4 h4 = fragA[(ksl * 8 + tmg) * 32 + lane];
                float4 l4 = fragA[512 + (ksl * 8 + tmg) * 32 + lane];
                aH[mt][0] = __float_as_uint(h4.x); aH[mt][1] = __float_as_uint(h4.y);
                aH[mt][2] = __float_as_uint(h4.z); aH[mt][3] = __float_as_uint(h4.w);
                aL[mt][0] = __float_as_uint(l4.x); aL[mt][1] = __float_as_uint(l4.y);
                aL[mt][2] = __float_as_uint(l4.z); aL[mt][3] = __float_as_uint(l4.w);
            }
            #pragma unroll
            for (int nt = 0; nt < 8; nt++) {
                int tng = wn * 8 + nt;
                float4 bf = W4[(ksl * 32 + tng) * 32 + lane];
                uint32_t bh0 = __float_as_uint(bf.x), bh1 = __float_as_uint(bf.y);
                uint32_t bl0 = __float_as_uint(bf.z), bl1 = __float_as_uint(bf.w);
                #pragma unroll
                for (int mt = 0; mt < 4; mt++) {
                    mmaf16(acc[mt][nt], aH[mt][0], aH[mt][1], aH[mt][2], aH[mt][3], bh0, bh1);
                    mmaf16(acc[mt][nt], aH[mt][0], aH[mt][1], aH[mt][2], aH[mt][3], bl0, bl1);
                    mmaf16(acc[mt][nt], aL[mt][0], aL[mt][1], aL[mt][2], aL[mt][3], bh0, bh1);
                }
            }
        }
        __syncthreads();
        if (ch + 2 < 16) ISSUE_W(ch + 2);
    }

    // ---- epilogue: bias, x fragments (k_dist A layout, f16), ||x||^2 ----
    int g = (n0 >> 6) + wm;                       // 64-token group per wm
    float4* xf4 = (float4*)g_xf + (size_t)g * 4096;
    float xnq[4], xnq8[4];
    #pragma unroll
    for (int mt = 0; mt < 4; mt++) { xnq[mt] = 0.f; xnq8[mt] = 0.f; }

    #pragma unroll
    for (int mt = 0; mt < 4; mt++) {
        #pragma unroll
        for (int ntp = 0; ntp < 4; ntp++) {       // nt pairs (even, odd)
            int ntE = ntp * 2, ntO = ntp * 2 + 1;
            int eE = wn * 64 + ntE * 8 + 2 * kq;
            int eO = wn * 64 + ntO * 8 + 2 * kq;
            float x0 = acc[mt][ntE][0] + sBias[eE];
            float x1 = acc[mt][ntE][1] + sBias[eE + 1];
            float x2 = acc[mt][ntE][2] + sBias[eE];
            float x3 = acc[mt][ntE][3] + sBias[eE + 1];
            float y0 = acc[mt][ntO][0] + sBias[eO];
            float y1 = acc[mt][ntO][1] + sBias[eO + 1];
            float y2 = acc[mt][ntO][2] + sBias[eO];
            float y3 = acc[mt][ntO][3] + sBias[eO + 1];
            xnq[mt]  += x0 * x0 + x1 * x1 + y0 * y0 + y1 * y1;
            xnq8[mt] += x2 * x2 + x3 * x3 + y2 * y2 + y3 * y3;
            // fragment: ks = e>>4 ; a0=(row q, eE pair) a1=(row q+8, eE) a2/(a3)=eO
            int ks = wn * 4 + ntp;
            uint32_t l0, l1, l2, l3;
            uint32_t h0 = packsplit(x0, x1, l0);
            uint32_t h1 = packsplit(x2, x3, l1);
            uint32_t h2 = packsplit(y0, y1, l2);
            uint32_t h3 = packsplit(y2, y3, l3);
            int idx = (ks * 4 + mt) * 32 + lane;
            xf4[idx]        = make_float4(__uint_as_float(h0), __uint_as_float(h1),
                                          __uint_as_float(h2), __uint_as_float(h3));
            xf4[2048 + idx] = make_float4(__uint_as_float(l0), __uint_as_float(l1),
                                          __uint_as_float(l2), __uint_as_float(l3));
        }
    }
    #pragma unroll
    for (int mt = 0; mt < 4; mt++) {
        float a = xnq[mt], b2 = xnq8[mt];
        a  += __shfl_xor_sync(0xffffffffu, a, 1);
        a  += __shfl_xor_sync(0xffffffffu, a, 2);
        b2 += __shfl_xor_sync(0xffffffffu, b2, 1);
        b2 += __shfl_xor_sync(0xffffffffu, b2, 2);
        if (kq == 0) {
            int tl = wm * 64 + mt * 16 + q;
            atomicAdd(&sXn[tl], a);
            atomicAdd(&sXn[tl + 8], b2);
        }
    }
    __syncthreads();
    if (tid < 128) g_xn[n0 + tid] = sXn[tid];
}

// ---------------------------------------------------------------
// distance via mma.sync f16x3 (m16n8k16): CTA = 64 tokens x 1024 codes
// 256 threads = 8 warps (2m x 4n); warp tile 32 tokens x 64 codes
// A resident (64KB), B 3-stage ring (3x16KB), one bar per chunk
// ---------------------------------------------------------------
#define DIST_DYN (65536 + 3 * 16384)
__global__ void __launch_bounds__(256, 2)
k_dist() {
    extern __shared__ char dyn[];
    float4* smA = (float4*)dyn;                         // 4096 f4

    int tid  = threadIdx.x;
    int wid  = tid >> 5, lane = tid & 31;
    int wm   = wid >> 2, wn = wid & 3;
    int q    = lane >> 2, kq = lane & 3;
    int g    = blockIdx.x;                              // 64-token group
    uint32_t smAu = smem_u32(dyn);
    uint32_t smBu = smAu + 65536;

    {
        const char* src = (const char*)((const float4*)g_xf + (size_t)g * 4096);
        for (int i = tid; i < 4096; i += 256)
            cp16(smAu + (uint32_t)i * 16, src + (size_t)i * 16);
        CP_COMMIT();
    }

    #define ISSUE(cc) do {                                                        \
        int _cgp = (cc) >> 4, _ks = (cc) & 15;                                    \
        const char* _s = (const char*)((const float4*)g_ef +                      \
                          ((size_t)(_cgp * 16 + _ks)) * 1024);                    \
        uint32_t _d = smBu + (uint32_t)((cc) % 3) * 16384;                        \
        for (int i = tid; i < 1024; i += 256)                                     \
            cp16(_d + (uint32_t)i * 16, _s + (size_t)i * 16);                     \
        CP_COMMIT();                                                              \
    } while (0)

    ISSUE(0);
    ISSUE(1);

    float acc[2][8][4];
    #pragma unroll
    for (int a = 0; a < 2; a++)
        #pragma unroll
        for (int b = 0; b < 8; b++)
            #pragma unroll
            for (int c = 0; c < 4; c++) acc[a][b][c] = 0.f;
    float bestv[4]; int besti[4];
    #pragma unroll
    for (int s = 0; s < 4; s++) { bestv[s] = 3.0e38f; besti[s] = 0; }

    for (int cc = 0; cc < 64; cc++) {
        if (cc + 1 < 64) CP_WAIT1(); else CP_WAIT0();
        __syncthreads();                 // publishes buf[cc]; retires buf[cc-1]
        if (cc + 2 < 64) ISSUE(cc + 2);
        const float4* B4 = (const float4*)(dyn + 65536 + (cc % 3) * 16384);
        int ks = cc & 15;
        uint32_t aH[2][4], aL[2][4];
        #pragma unroll
        for (int tm2 = 0; tm2 < 2; tm2++) {
            int tmg = wm * 2 + tm2;
            float4 h4 = smA[(ks * 4 + tmg) * 32 + lane];
            float4 l4 = smA[2048 + (ks * 4 + tmg) * 32 + lane];
            aH[tm2][0] = __float_as_uint(h4.x); aH[tm2][1] = __float_as_uint(h4.y);
            aH[tm2][2] = __float_as_uint(h4.z); aH[tm2][3] = __float_as_uint(h4.w);
            aL[tm2][0] = __float_as_uint(l4.x); aL[tm2][1] = __float_as_uint(l4.y);
            aL[tm2][2] = __float_as_uint(l4.z); aL[tm2][3] = __float_as_uint(l4.w);
        }
        #pragma unroll
        for (int tn = 0; tn < 8; tn++) {
            int tng = wn * 8 + tn;
            float4 bf = B4[tng * 32 + lane];
            uint32_t bh0 = __float_as_uint(bf.x), bh1 = __float_as_uint(bf.y);
            uint32_t bl0 = __float_as_uint(bf.z), bl1 = __float_as_uint(bf.w);
            #pragma unroll
            for (int tm2 = 0; tm2 < 2; tm2++) {
                mmaf16(acc[tm2][tn], aH[tm2][0], aH[tm2][1], aH[tm2][2], aH[tm2][3], bh0, bh1);
                mmaf16(acc[tm2][tn], aH[tm2][0], aH[tm2][1], aH[tm2][2], aH[tm2][3], bl0, bl1);
                mmaf16(acc[tm2][tn], aL[tm2][0], aL[tm2][1], aL[tm2][2], aL[tm2][3], bh0, bh1);
            }
        }
        if (ks == 15) {
            int cgp = cc >> 4;
            #pragma unroll
            for (int tn = 0; tn < 8; tn++) {
                int tng = wn * 8 + tn;
                int nb = cgp * 256 + tng * 8 + 2 * kq;
                float e0v = __ldg(&g_enorm[nb]);
                float e1v = __ldg(&g_enorm[nb + 1]);
                #pragma unroll
                for (int tm2 = 0; tm2 < 2; tm2++) {
                    float s00 = fmaf(-2.0f, acc[tm2][tn][0], e0v);
                    float s01 = fmaf(-2.0f, acc[tm2][tn][1], e1v);
                    float s10 = fmaf(-2.0f, acc[tm2][tn][2], e0v);
                    float s11 = fmaf(-2.0f, acc[tm2][tn][3], e1v);
                    int s0 = tm2 * 2, s1 = tm2 * 2 + 1;
                    if (s00 < bestv[s0]) { bestv[s0] = s00; besti[s0] = nb; }
                    if (s01 < bestv[s0]) { bestv[s0] = s01; besti[s0] = nb + 1; }
                    if (s10 < bestv[s1]) { bestv[s1] = s10; besti[s1] = nb; }
                    if (s11 < bestv[s1]) { bestv[s1] = s11; besti[s1] = nb + 1; }
                    acc[tm2][tn][0] = 0.f; acc[tm2][tn][1] = 0.f;
                    acc[tm2][tn][2] = 0.f; acc[tm2][tn][3] = 0.f;
                }
            }
        }
    }
    __syncthreads();                     // compute done; reuse B ring
    float* redv = (float*)(dyn + 65536);            // 64*4 floats
    int*   redi = (int*)(dyn + 65536 + 1024);       // 64*4 ints
    float* lred = (float*)(dyn + 65536 + 2048);     // 2 floats

    #pragma unroll
    for (int s = 0; s < 4; s++) {
        float v = bestv[s]; int bi = besti[s];
        #pragma unroll
        for (int off = 1; off <= 2; off <<= 1) {
            float ov = __shfl_xor_sync(0xffffffffu, v, off);
            int   oi = __shfl_xor_sync(0xffffffffu, bi, off);
            if (ov < v || (ov == v && oi < bi)) { v = ov; bi = oi; }
        }
        if ((lane & 3) == 0) {
            int row = wm * 32 + (s >> 1) * 16 + (s & 1) * 8 + q;
            redv[row * 4 + wn] = v;
            redi[row * 4 + wn] = bi;
        }
    }
    __syncthreads();
    float myd2 = 0.f;
    if (tid < 64) {
        float v = redv[tid * 4]; int bi = redi[tid * 4];
        #pragma unroll
        for (int j = 1; j < 4; j++) {
            float ov = redv[tid * 4 + j]; int oi = redi[tid * 4 + j];
            if (ov < v || (ov == v && oi < bi)) { v = ov; bi = oi; }
        }
        int n = g * 64 + tid;
        g_idx[n] = bi;
        atomicAdd(&g_hist[bi], 1);
        myd2 = g_xn[n] + v;                    // ||x||^2 + (||e||^2 - 2x.e)
    }
    for (int o = 16; o > 0; o >>= 1) myd2 += __shfl_down_sync(0xffffffffu, myd2, o);
    if ((tid & 31) == 0 && wid < 2) lred[wid] = myd2;
    __syncthreads();
    if (tid == 0) atomicAdd(&g_mse, (double)(lred[0] + lred[1]));
}

// ---------------------------------------------------------------
// output: z_q_out[b,e,t] = embed[q_idx[b*T+t]][e]  (32x32 transpose)
// ---------------------------------------------------------------
__global__ void k_out(const float* __restrict__ embed, float* __restrict__ out) {
    __shared__ int   qs[32];
    __shared__ float sm[32][33];
    int b  = blockIdx.z;
    int e0 = blockIdx.y * 32;
    int t0 = blockIdx.x * 32;
    int tid = threadIdx.x;
    if (tid < 32) qs[tid] = g_idx[b * Tt + t0 + tid];
    __syncthreads();
    {
        int j = tid >> 3, gg = tid & 7;
        const float4* erow = (const float4*)(embed + (size_t)qs[j] * Ee + e0);
        float4 v = erow[gg];
        sm[j][gg * 4 + 0] = v.x; sm[j][gg * 4 + 1] = v.y;
        sm[j][gg * 4 + 2] = v.z; sm[j][gg * 4 + 3] = v.w;
    }
    __syncthreads();
    int tl = tid & 31, eb = tid >> 5;
    #pragma unroll
    for (int r = 0; r < 4; r++) {
        int el = eb + r * 8;
        out[((size_t)b * Ee + e0 + el) * Tt + t0 + tl] = sm[tl][el];
    }
}

// ---------------------------------------------------------------
// tail scalars
// ---------------------------------------------------------------
__global__ void k_tail(float* __restrict__ out) {
    __shared__ float red[32];
    int tid = threadIdx.x;                     // 1024
    float p = (float)g_hist[tid] / 65536.0f;
    float term = -p * logf(p + 1e-10f);
    for (int o = 16; o > 0; o >>= 1) term += __shfl_down_sync(0xffffffffu, term, o);
    if ((tid & 31) == 0) red[tid >> 5] = term;
    __syncthreads();
    const size_t base = (size_t)Bb * Ee * Tt;
    if (tid == 0) {
        float lp = 0.f;
        #pragma unroll
        for (int i = 0; i < 32; i++) lp += red[i];
        out[base + 0]  = (float)(1.25 * (g_mse / (double)((size_t)NTOK * Ee)));
        out[base + 17] = lp;
    }
    if (tid < 16) out[base + 1 + tid] = (float)(log(1024.0) * 4096.0);
}

// ---------------------------------------------------------------
extern "C" void kernel_launch(void* const* d_in, const int* in_sizes, int n_in,
                              void* d_out, int out_size) {
    const float* inputs = (const float*)d_in[0];   // [16, 512, 4096]
    const float* proj_w = (const float*)d_in[1];   // [256, 512]
    const float* proj_b = (const float*)d_in[2];   // [256]
    const float* embed  = (const float*)d_in[3];   // [1024, 256]
    float* out = (float*)d_out;

    cudaFuncSetAttribute(k_proj, cudaFuncAttributeMaxDynamicSharedMemorySize, PROJ_DYN);
    cudaFuncSetAttribute(k_dist, cudaFuncAttributeMaxDynamicSharedMemorySize, DIST_DYN);

    k_init<<<NE, 256>>>(embed);
    k_winit<<<Cc, 256>>>(proj_w);
    k_proj<<<NTOK / 128, 256, PROJ_DYN>>>(inputs, proj_b);
    k_dist<<<NTOK / 64, 256, DIST_DYN>>>();
    dim3 g3(Tt / 32, Ee / 32, Bb);
    k_out<<<g3, 256>>>(embed, out);
    k_tail<<<1, 1024>>>(out);
}

// round 11
// speedup vs baseline: 2.3778x; 1.0677x over previous
#include <cuda_runtime.h>
#include <cuda_fp16.h>
#include <math.h>
#include <cstdint>

#define Bb   16
#define Tt   4096
#define Cc   512
#define Ee   256
#define NE   1024
#define NTOK (Bb*Tt)

// ---- scratch (static device memory) ----
// x fragments (f16 hi/lo): per 64-token group (64KB = 4096 float4):
//   [hi: (ks16*4+tm)*32+lane][lo: +2048]  float4 = {a0,a1,a2,a3} packed f16x2
__device__ __align__(16) float g_xf[(size_t)NTOK * Ee];
// embed fragments (f16): [cgp(4)][ks(16)][tn(32)][lane(32)] float4 = {b0h,b1h,b0l,b1l}
__device__ __align__(16) float g_ef[(size_t)NE * Ee];
// proj-weight fragments (f16): [ks(32)][tn(32)][lane(32)] float4
__device__ __align__(16) float g_wf[(size_t)Ee * Cc];
__device__ float  g_enorm[NE];
__device__ float  g_xn[NTOK];       // per-token ||x||^2
__device__ int    g_idx[NTOK];
__device__ int    g_hist[NE];
__device__ double g_mse;            // sum of d2_min over tokens

// ---------------- helpers ----------------
__device__ __forceinline__ uint32_t smem_u32(const void* p) {
    uint32_t a;
    asm("{ .reg .u64 t; cvta.to.shared.u64 t, %1; cvt.u32.u64 %0, t; }" : "=r"(a) : "l"(p));
    return a;
}
// split two floats into packed f16x2 hi + f16x2 lo
__device__ __forceinline__ uint32_t packsplit(float x0, float x1, uint32_t& lo) {
    __half h0 = __float2half_rn(x0);
    __half l0 = __float2half_rn(x0 - __half2float(h0));
    __half h1 = __float2half_rn(x1);
    __half l1 = __float2half_rn(x1 - __half2float(h1));
    __half2 hh = __halves2half2(h0, h1), ll = __halves2half2(l0, l1);
    lo = *(uint32_t*)&ll;
    return *(uint32_t*)&hh;
}
__device__ __forceinline__ void mmaf16(float* d, uint32_t a0, uint32_t a1,
                                       uint32_t a2, uint32_t a3,
                                       uint32_t b0, uint32_t b1) {
    asm volatile(
        "mma.sync.aligned.m16n8k16.row.col.f32.f16.f16.f32 "
        "{%0,%1,%2,%3}, {%4,%5,%6,%7}, {%8,%9}, {%0,%1,%2,%3};"
        : "+f"(d[0]), "+f"(d[1]), "+f"(d[2]), "+f"(d[3])
        : "r"(a0), "r"(a1), "r"(a2), "r"(a3), "r"(b0), "r"(b1));
}
__device__ __forceinline__ void cp16(uint32_t s, const void* g) {
    asm volatile("cp.async.cg.shared.global [%0], [%1], 16;" :: "r"(s), "l"(g));
}
#define CP_COMMIT() asm volatile("cp.async.commit_group;" ::: "memory")
#define CP_WAIT1()  asm volatile("cp.async.wait_group 1;" ::: "memory")
#define CP_WAIT0()  asm volatile("cp.async.wait_group 0;" ::: "memory")

// ---------------------------------------------------------------
// init: ||e||^2, embed f16 hi/lo fragments, zero hist/mse
// ---------------------------------------------------------------
__global__ void k_init(const float* __restrict__ embed) {
    int c = blockIdx.x;                 // code 0..1023
    int e = threadIdx.x;                // k 0..255
    float v = embed[(size_t)c * Ee + e];
    __half h = __float2half_rn(v);
    __half l = __float2half_rn(v - __half2float(h));
    int cgp = c >> 8, cl = c & 255, tn = cl >> 3, qq = cl & 7;
    int ks = e >> 4, r = e & 15, kq = (r >> 1) & 3, odd = r & 1, b1f = r >> 3;
    int lane = qq * 4 + kq;
    size_t f4 = (((size_t)cgp * 16 + ks) * 32 + tn) * 32 + lane;
    __half* hp = (__half*)g_ef;
    hp[f4 * 8 + b1f * 2 + odd]     = h;
    hp[f4 * 8 + 4 + b1f * 2 + odd] = l;

    float s = v * v;
    __shared__ float red[8];
    for (int o = 16; o > 0; o >>= 1) s += __shfl_down_sync(0xffffffffu, s, o);
    if ((e & 31) == 0) red[e >> 5] = s;
    __syncthreads();
    if (e == 0) {
        float t = 0.f;
        #pragma unroll
        for (int i = 0; i < 8; i++) t += red[i];
        g_enorm[c] = t;
        g_hist[c]  = 0;
        if (c == 0) g_mse = 0.0;
    }
}

// ---------------------------------------------------------------
// winit: proj weight f16 hi/lo fragments (B operand layout)
// ---------------------------------------------------------------
__global__ void k_winit(const float* __restrict__ w) {
    int c = blockIdx.x;                 // 0..511 (k dim)
    int e = threadIdx.x;                // 0..255 (n dim)
    float v = w[(size_t)e * Cc + c];
    __half h = __float2half_rn(v);
    __half l = __float2half_rn(v - __half2float(h));
    int ks = c >> 4, r = c & 15, kq = (r >> 1) & 3, odd = r & 1, b1f = r >> 3;
    int tn = e >> 3, qq = e & 7;
    int lane = qq * 4 + kq;
    size_t f4 = ((size_t)ks * 32 + tn) * 32 + lane;
    __half* hp = (__half*)g_wf;
    hp[f4 * 8 + b1f * 2 + odd]     = h;
    hp[f4 * 8 + 4 + b1f * 2 + odd] = l;
}

// ---------------------------------------------------------------
// projection via mma.sync f16x3: CTA = 64 tokens x 256 feats, occ 2
// 256 threads = 8 warps (2m x 4n); warp tile 32 tokens x 64 feats
// k16 chunks (32), W 3-ring cp.async, A double-buffered smem stage,
// ONE barrier per chunk
// ---------------------------------------------------------------
#define PROJ_DYN (8192 + 3 * 16384)
__global__ void __launch_bounds__(256, 2)
k_proj(const float* __restrict__ in, const float* __restrict__ bias) {
    extern __shared__ char dyn[];
    float*  fragAf = (float*)dyn;                    // 2 bufs x 1024 floats (hi 512 | lo 512)
    float4* fragA4 = (float4*)dyn;
    __shared__ float sBias[256];
    __shared__ float sXn[64];

    int tid  = threadIdx.x;
    int lane = tid & 31, wid = tid >> 5;
    int wm   = wid >> 2, wn = wid & 3;
    int q    = lane >> 2, kq = lane & 3;
    int g    = blockIdx.x;                           // 64-token group
    int n0   = g * 64;
    int b    = n0 >> 12, t0 = n0 & 4095;
    const float* inb = in + (size_t)b * Cc * Tt + t0;
    uint32_t smWu = smem_u32(dyn) + 8192;

    sBias[tid] = bias[tid];
    if (tid < 64) sXn[tid] = 0.f;

    // A-fill thread mapping: akq(c-quad), aq(row), atm(t-tile), khalf(k8 half)
    int akq = tid & 3, aq = (tid >> 2) & 7, atm = (tid >> 5) & 3, khalf = tid >> 7;

    #define ISSUE_W(ch) do {                                                      \
        const char* _s = (const char*)((const float4*)g_wf + (size_t)(ch)*1024);  \
        uint32_t _d = smWu + (uint32_t)((ch) % 3) * 16384;                        \
        for (int i = tid; i < 1024; i += 256)                                     \
            cp16(_d + (uint32_t)i * 16, _s + (size_t)i * 16);                     \
        CP_COMMIT();                                                              \
    } while (0)

    #define LDG_A(ch, v) do {                                                     \
        const float* _p = inb + (size_t)((ch) * 16 + khalf * 8 + 2 * akq) * Tt    \
                              + atm * 16 + aq;                                    \
        (v)[0] = _p[0];  (v)[1] = _p[Tt];                                         \
        (v)[2] = _p[8];  (v)[3] = _p[Tt + 8];                                     \
    } while (0)

    #define STS_A(buf, v) do {                                                    \
        uint32_t _l0, _l1;                                                        \
        uint32_t _h0 = packsplit((v)[0], (v)[1], _l0);                            \
        uint32_t _h1 = packsplit((v)[2], (v)[3], _l1);                            \
        int _o = (buf) * 1024 + (atm * 32 + aq * 4 + akq) * 4 + khalf * 2;        \
        *(uint2*)&fragAf[_o]       = make_uint2(_h0, _h1);                        \
        *(uint2*)&fragAf[_o + 512] = make_uint2(_l0, _l1);                        \
    } while (0)

    // prologue: stage A chunk 0, start W ring
    {
        float v[4];
        LDG_A(0, v);
        STS_A(0, v);
    }
    ISSUE_W(0);
    ISSUE_W(1);

    float acc[2][8][4];
    #pragma unroll
    for (int a = 0; a < 2; a++)
        #pragma unroll
        for (int bb = 0; bb < 8; bb++)
            #pragma unroll
            for (int cix = 0; cix < 4; cix++) acc[a][bb][cix] = 0.f;

    for (int ch = 0; ch < 32; ch++) {
        if (ch < 31) CP_WAIT1(); else CP_WAIT0();
        __syncthreads();                 // publishes fragA[ch&1] + W(ch); retires W(ch-1) reads
        if (ch + 2 < 32) ISSUE_W(ch + 2);
        float v[4];
        if (ch < 31) LDG_A(ch + 1, v);   // issue loads early; consumed after MMAs

        const float4* W4 = (const float4*)(dyn + 8192 + (ch % 3) * 16384);
        uint32_t aH[2][4], aL[2][4];
        #pragma unroll
        for (int mt = 0; mt < 2; mt++) {
            int tmg = wm * 2 + mt;
            float4 h4 = fragA4[(ch & 1) * 256 + tmg * 32 + lane];
            float4 l4 = fragA4[(ch & 1) * 256 + 128 + tmg * 32 + lane];
            aH[mt][0] = __float_as_uint(h4.x); aH[mt][1] = __float_as_uint(h4.y);
            aH[mt][2] = __float_as_uint(h4.z); aH[mt][3] = __float_as_uint(h4.w);
            aL[mt][0] = __float_as_uint(l4.x); aL[mt][1] = __float_as_uint(l4.y);
            aL[mt][2] = __float_as_uint(l4.z); aL[mt][3] = __float_as_uint(l4.w);
        }
        #pragma unroll
        for (int nt = 0; nt < 8; nt++) {
            int tng = wn * 8 + nt;
            float4 bf = W4[tng * 32 + lane];
            uint32_t bh0 = __float_as_uint(bf.x), bh1 = __float_as_uint(bf.y);
            uint32_t bl0 = __float_as_uint(bf.z), bl1 = __float_as_uint(bf.w);
            #pragma unroll
            for (int mt = 0; mt < 2; mt++) {
                mmaf16(acc[mt][nt], aH[mt][0], aH[mt][1], aH[mt][2], aH[mt][3], bh0, bh1);
                mmaf16(acc[mt][nt], aH[mt][0], aH[mt][1], aH[mt][2], aH[mt][3], bl0, bl1);
                mmaf16(acc[mt][nt], aL[mt][0], aL[mt][1], aL[mt][2], aL[mt][3], bh0, bh1);
            }
        }
        if (ch < 31) STS_A((ch + 1) & 1, v);   // fill next buf (WAR-free: other parity)
    }

    // ---- epilogue: bias, x fragments (k_dist A layout, f16), ||x||^2 ----
    float4* xf4 = (float4*)g_xf + (size_t)g * 4096;
    #pragma unroll
    for (int mt = 0; mt < 2; mt++) {
        int tmg = wm * 2 + mt;
        float xnq = 0.f, xnq8 = 0.f;
        #pragma unroll
        for (int ntp = 0; ntp < 4; ntp++) {       // nt pairs (even, odd)
            int ntE = ntp * 2, ntO = ntp * 2 + 1;
            int eE = wn * 64 + ntE * 8 + 2 * kq;
            int eO = wn * 64 + ntO * 8 + 2 * kq;
            float x0 = acc[mt][ntE][0] + sBias[eE];
            float x1 = acc[mt][ntE][1] + sBias[eE + 1];
            float x2 = acc[mt][ntE][2] + sBias[eE];
            float x3 = acc[mt][ntE][3] + sBias[eE + 1];
            float y0 = acc[mt][ntO][0] + sBias[eO];
            float y1 = acc[mt][ntO][1] + sBias[eO + 1];
            float y2 = acc[mt][ntO][2] + sBias[eO];
            float y3 = acc[mt][ntO][3] + sBias[eO + 1];
            xnq  += x0 * x0 + x1 * x1 + y0 * y0 + y1 * y1;
            xnq8 += x2 * x2 + x3 * x3 + y2 * y2 + y3 * y3;
            int ks = wn * 4 + ntp;
            uint32_t l0, l1, l2, l3;
            uint32_t h0 = packsplit(x0, x1, l0);
            uint32_t h1 = packsplit(x2, x3, l1);
            uint32_t h2 = packsplit(y0, y1, l2);
            uint32_t h3 = packsplit(y2, y3, l3);
            int idx = (ks * 4 + tmg) * 32 + lane;
            xf4[idx]        = make_float4(__uint_as_float(h0), __uint_as_float(h1),
                                          __uint_as_float(h2), __uint_as_float(h3));
            xf4[2048 + idx] = make_float4(__uint_as_float(l0), __uint_as_float(l1),
                                          __uint_as_float(l2), __uint_as_float(l3));
        }
        xnq  += __shfl_xor_sync(0xffffffffu, xnq, 1);
        xnq  += __shfl_xor_sync(0xffffffffu, xnq, 2);
        xnq8 += __shfl_xor_sync(0xffffffffu, xnq8, 1);
        xnq8 += __shfl_xor_sync(0xffffffffu, xnq8, 2);
        if (kq == 0) {
            int tl = wm * 32 + mt * 16 + q;
            atomicAdd(&sXn[tl], xnq);
            atomicAdd(&sXn[tl + 8], xnq8);
        }
    }
    __syncthreads();
    if (tid < 64) g_xn[n0 + tid] = sXn[tid];
}

// ---------------------------------------------------------------
// distance via mma.sync f16x3 (m16n8k16): CTA = 64 tokens x 1024 codes
// 256 threads = 8 warps (2m x 4n); warp tile 32 tokens x 64 codes
// A resident (64KB), B 3-stage ring (3x16KB), one bar per chunk
// ---------------------------------------------------------------
#define DIST_DYN (65536 + 3 * 16384)
__global__ void __launch_bounds__(256, 2)
k_dist() {
    extern __shared__ char dyn[];
    float4* smA = (float4*)dyn;                         // 4096 f4

    int tid  = threadIdx.x;
    int wid  = tid >> 5, lane = tid & 31;
    int wm   = wid >> 2, wn = wid & 3;
    int q    = lane >> 2, kq = lane & 3;
    int g    = blockIdx.x;                              // 64-token group
    uint32_t smAu = smem_u32(dyn);
    uint32_t smBu = smAu + 65536;

    {
        const char* src = (const char*)((const float4*)g_xf + (size_t)g * 4096);
        for (int i = tid; i < 4096; i += 256)
            cp16(smAu + (uint32_t)i * 16, src + (size_t)i * 16);
        CP_COMMIT();
    }

    #define ISSUE(cc) do {                                                        \
        int _cgp = (cc) >> 4, _ks = (cc) & 15;                                    \
        const char* _s = (const char*)((const float4*)g_ef +                      \
                          ((size_t)(_cgp * 16 + _ks)) * 1024);                    \
        uint32_t _d = smBu + (uint32_t)((cc) % 3) * 16384;                        \
        for (int i = tid; i < 1024; i += 256)                                     \
            cp16(_d + (uint32_t)i * 16, _s + (size_t)i * 16);                     \
        CP_COMMIT();                                                              \
    } while (0)

    ISSUE(0);
    ISSUE(1);

    float acc[2][8][4];
    #pragma unroll
    for (int a = 0; a < 2; a++)
        #pragma unroll
        for (int b = 0; b < 8; b++)
            #pragma unroll
            for (int c = 0; c < 4; c++) acc[a][b][c] = 0.f;
    float bestv[4]; int besti[4];
    #pragma unroll
    for (int s = 0; s < 4; s++) { bestv[s] = 3.0e38f; besti[s] = 0; }

    for (int cc = 0; cc < 64; cc++) {
        if (cc + 1 < 64) CP_WAIT1(); else CP_WAIT0();
        __syncthreads();                 // publishes buf[cc]; retires buf[cc-1]
        if (cc + 2 < 64) ISSUE(cc + 2);
        const float4* B4 = (const float4*)(dyn + 65536 + (cc % 3) * 16384);
        int ks = cc & 15;
        uint32_t aH[2][4], aL[2][4];
        #pragma unroll
        for (int tm2 = 0; tm2 < 2; tm2++) {
            int tmg = wm * 2 + tm2;
            float4 h4 = smA[(ks * 4 + tmg) * 32 + lane];
            float4 l4 = smA[2048 + (ks * 4 + tmg) * 32 + lane];
            aH[tm2][0] = __float_as_uint(h4.x); aH[tm2][1] = __float_as_uint(h4.y);
            aH[tm2][2] = __float_as_uint(h4.z); aH[tm2][3] = __float_as_uint(h4.w);
            aL[tm2][0] = __float_as_uint(l4.x); aL[tm2][1] = __float_as_uint(l4.y);
            aL[tm2][2] = __float_as_uint(l4.z); aL[tm2][3] = __float_as_uint(l4.w);
        }
        #pragma unroll
        for (int tn = 0; tn < 8; tn++) {
            int tng = wn * 8 + tn;
            float4 bf = B4[tng * 32 + lane];
            uint32_t bh0 = __float_as_uint(bf.x), bh1 = __float_as_uint(bf.y);
            uint32_t bl0 = __float_as_uint(bf.z), bl1 = __float_as_uint(bf.w);
            #pragma unroll
            for (int tm2 = 0; tm2 < 2; tm2++) {
                mmaf16(acc[tm2][tn], aH[tm2][0], aH[tm2][1], aH[tm2][2], aH[tm2][3], bh0, bh1);
                mmaf16(acc[tm2][tn], aH[tm2][0], aH[tm2][1], aH[tm2][2], aH[tm2][3], bl0, bl1);
                mmaf16(acc[tm2][tn], aL[tm2][0], aL[tm2][1], aL[tm2][2], aL[tm2][3], bh0, bh1);
            }
        }
        if (ks == 15) {
            int cgp = cc >> 4;
            #pragma unroll
            for (int tn = 0; tn < 8; tn++) {
                int tng = wn * 8 + tn;
                int nb = cgp * 256 + tng * 8 + 2 * kq;
                float e0v = __ldg(&g_enorm[nb]);
                float e1v = __ldg(&g_enorm[nb + 1]);
                #pragma unroll
                for (int tm2 = 0; tm2 < 2; tm2++) {
                    float s00 = fmaf(-2.0f, acc[tm2][tn][0], e0v);
                    float s01 = fmaf(-2.0f, acc[tm2][tn][1], e1v);
                    float s10 = fmaf(-2.0f, acc[tm2][tn][2], e0v);
                    float s11 = fmaf(-2.0f, acc[tm2][tn][3], e1v);
                    int s0 = tm2 * 2, s1 = tm2 * 2 + 1;
                    if (s00 < bestv[s0]) { bestv[s0] = s00; besti[s0] = nb; }
                    if (s01 < bestv[s0]) { bestv[s0] = s01; besti[s0] = nb + 1; }
                    if (s10 < bestv[s1]) { bestv[s1] = s10; besti[s1] = nb; }
                    if (s11 < bestv[s1]) { bestv[s1] = s11; besti[s1] = nb + 1; }
                    acc[tm2][tn][0] = 0.f; acc[tm2][tn][1] = 0.f;
                    acc[tm2][tn][2] = 0.f; acc[tm2][tn][3] = 0.f;
                }
            }
        }
    }
    __syncthreads();                     // compute done; reuse B ring
    float* redv = (float*)(dyn + 65536);            // 64*4 floats
    int*   redi = (int*)(dyn + 65536 + 1024);       // 64*4 ints
    float* lred = (float*)(dyn + 65536 + 2048);     // 2 floats

    #pragma unroll
    for (int s = 0; s < 4; s++) {
        float v = bestv[s]; int bi = besti[s];
        #pragma unroll
        for (int off = 1; off <= 2; off <<= 1) {
            float ov = __shfl_xor_sync(0xffffffffu, v, off);
            int   oi = __shfl_xor_sync(0xffffffffu, bi, off);
            if (ov < v || (ov == v && oi < bi)) { v = ov; bi = oi; }
        }
        if ((lane & 3) == 0) {
            int row = wm * 32 + (s >> 1) * 16 + (s & 1) * 8 + q;
            redv[row * 4 + wn] = v;
            redi[row * 4 + wn] = bi;
        }
    }
    __syncthreads();
    float myd2 = 0.f;
    if (tid < 64) {
        float v = redv[tid * 4]; int bi = redi[tid * 4];
        #pragma unroll
        for (int j = 1; j < 4; j++) {
            float ov = redv[tid * 4 + j]; int oi = redi[tid * 4 + j];
            if (ov < v || (ov == v && oi < bi)) { v = ov; bi = oi; }
        }
        int n = g * 64 + tid;
        g_idx[n] = bi;
        atomicAdd(&g_hist[bi], 1);
        myd2 = g_xn[n] + v;                    // ||x||^2 + (||e||^2 - 2x.e)
    }
    for (int o = 16; o > 0; o >>= 1) myd2 += __shfl_down_sync(0xffffffffu, myd2, o);
    if ((tid & 31) == 0 && wid < 2) lred[wid] = myd2;
    __syncthreads();
    if (tid == 0) atomicAdd(&g_mse, (double)(lred[0] + lred[1]));
}

// ---------------------------------------------------------------
// output: z_q_out[b,e,t] = embed[q_idx[b*T+t]][e]  (32x32 transpose)
// ---------------------------------------------------------------
__global__ void k_out(const float* __restrict__ embed, float* __restrict__ out) {
    __shared__ int   qs[32];
    __shared__ float sm[32][33];
    int b  = blockIdx.z;
    int e0 = blockIdx.y * 32;
    int t0 = blockIdx.x * 32;
    int tid = threadIdx.x;
    if (tid < 32) qs[tid] = g_idx[b * Tt + t0 + tid];
    __syncthreads();
    {
        int j = tid >> 3, gg = tid & 7;
        const float4* erow = (const float4*)(embed + (size_t)qs[j] * Ee + e0);
        float4 v = erow[gg];
        sm[j][gg * 4 + 0] = v.x; sm[j][gg * 4 + 1] = v.y;
        sm[j][gg * 4 + 2] = v.z; sm[j][gg * 4 + 3] = v.w;
    }
    __syncthreads();
    int tl = tid & 31, eb = tid >> 5;
    #pragma unroll
    for (int r = 0; r < 4; r++) {
        int el = eb + r * 8;
        out[((size_t)b * Ee + e0 + el) * Tt + t0 + tl] = sm[tl][el];
    }
}

// ---------------------------------------------------------------
// tail scalars
// ---------------------------------------------------------------
__global__ void k_tail(float* __restrict__ out) {
    __shared__ float red[32];
    int tid = threadIdx.x;                     // 1024
    float p = (float)g_hist[tid] / 65536.0f;
    float term = -p * logf(p + 1e-10f);
    for (int o = 16; o > 0; o >>= 1) term += __shfl_down_sync(0xffffffffu, term, o);
    if ((tid & 31) == 0) red[tid >> 5] = term;
    __syncthreads();
    const size_t base = (size_t)Bb * Ee * Tt;
    if (tid == 0) {
        float lp = 0.f;
        #pragma unroll
        for (int i = 0; i < 32; i++) lp += red[i];
        out[base + 0]  = (float)(1.25 * (g_mse / (double)((size_t)NTOK * Ee)));
        out[base + 17] = lp;
    }
    if (tid < 16) out[base + 1 + tid] = (float)(log(1024.0) * 4096.0);
}

// ---------------------------------------------------------------
extern "C" void kernel_launch(void* const* d_in, const int* in_sizes, int n_in,
                              void* d_out, int out_size) {
    const float* inputs = (const float*)d_in[0];   // [16, 512, 4096]
    const float* proj_w = (const float*)d_in[1];   // [256, 512]
    const float* proj_b = (const float*)d_in[2];   // [256]
    const float* embed  = (const float*)d_in[3];   // [1024, 256]
    float* out = (float*)d_out;

    cudaFuncSetAttribute(k_proj, cudaFuncAttributeMaxDynamicSharedMemorySize, PROJ_DYN);
    cudaFuncSetAttribute(k_dist, cudaFuncAttributeMaxDynamicSharedMemorySize, DIST_DYN);

    k_init<<<NE, 256>>>(embed);
    k_winit<<<Cc, 256>>>(proj_w);
    k_proj<<<NTOK / 64, 256, PROJ_DYN>>>(inputs, proj_b);
    k_dist<<<NTOK / 64, 256, DIST_DYN>>>();
    dim3 g3(Tt / 32, Ee / 32, Bb);
    k_out<<<g3, 256>>>(embed, out);
    k_tail<<<1, 1024>>>(out);
}

// round 13
// speedup vs baseline: 2.5513x; 1.0730x over previous
#include <cuda_runtime.h>
#include <cuda_fp16.h>
#include <math.h>
#include <cstdint>

#define Bb   16
#define Tt   4096
#define Cc   512
#define Ee   256
#define NE   1024
#define NTOK (Bb*Tt)

// ---- scratch (static device memory) ----
// embed fragments (f16): [cgp(4)][ks(16)][tn(32)][lane(32)] float4 = {b0h,b1h,b0l,b1l}
__device__ __align__(16) float g_ef[(size_t)NE * Ee];
// proj-weight fragments (f16): [ks(32)][tn(32)][lane(32)] float4
__device__ __align__(16) float g_wf[(size_t)Ee * Cc];
__device__ float  g_enorm[NE];
__device__ int    g_idx[NTOK];
__device__ int    g_hist[NE];
__device__ double g_mse;            // sum of d2_min over tokens

// ---------------- helpers ----------------
__device__ __forceinline__ uint32_t smem_u32(const void* p) {
    uint32_t a;
    asm("{ .reg .u64 t; cvta.to.shared.u64 t, %1; cvt.u32.u64 %0, t; }" : "=r"(a) : "l"(p));
    return a;
}
// split two floats into packed f16x2 hi + f16x2 lo
__device__ __forceinline__ uint32_t packsplit(float x0, float x1, uint32_t& lo) {
    __half h0 = __float2half_rn(x0);
    __half l0 = __float2half_rn(x0 - __half2float(h0));
    __half h1 = __float2half_rn(x1);
    __half l1 = __float2half_rn(x1 - __half2float(h1));
    __half2 hh = __halves2half2(h0, h1), ll = __halves2half2(l0, l1);
    lo = *(uint32_t*)&ll;
    return *(uint32_t*)&hh;
}
__device__ __forceinline__ void mmaf16(float* d, uint32_t a0, uint32_t a1,
                                       uint32_t a2, uint32_t a3,
                                       uint32_t b0, uint32_t b1) {
    asm volatile(
        "mma.sync.aligned.m16n8k16.row.col.f32.f16.f16.f32 "
        "{%0,%1,%2,%3}, {%4,%5,%6,%7}, {%8,%9}, {%0,%1,%2,%3};"
        : "+f"(d[0]), "+f"(d[1]), "+f"(d[2]), "+f"(d[3])
        : "r"(a0), "r"(a1), "r"(a2), "r"(a3), "r"(b0), "r"(b1));
}
__device__ __forceinline__ void cp16(uint32_t s, const void* g) {
    asm volatile("cp.async.cg.shared.global [%0], [%1], 16;" :: "r"(s), "l"(g));
}
#define CP_COMMIT() asm volatile("cp.async.commit_group;" ::: "memory")
#define CP_WAIT1()  asm volatile("cp.async.wait_group 1;" ::: "memory")
#define CP_WAIT0()  asm volatile("cp.async.wait_group 0;" ::: "memory")

// ---------------------------------------------------------------
// init: ||e||^2, embed f16 hi/lo fragments, zero hist/mse
// ---------------------------------------------------------------
__global__ void k_init(const float* __restrict__ embed) {
    int c = blockIdx.x;                 // code 0..1023
    int e = threadIdx.x;                // k 0..255
    float v = embed[(size_t)c * Ee + e];
    __half h = __float2half_rn(v);
    __half l = __float2half_rn(v - __half2float(h));
    int cgp = c >> 8, cl = c & 255, tn = cl >> 3, qq = cl & 7;
    int ks = e >> 4, r = e & 15, kq = (r >> 1) & 3, odd = r & 1, b1f = r >> 3;
    int lane = qq * 4 + kq;
    size_t f4 = (((size_t)cgp * 16 + ks) * 32 + tn) * 32 + lane;
    __half* hp = (__half*)g_ef;
    hp[f4 * 8 + b1f * 2 + odd]     = h;
    hp[f4 * 8 + 4 + b1f * 2 + odd] = l;

    float s = v * v;
    __shared__ float red[8];
    for (int o = 16; o > 0; o >>= 1) s += __shfl_down_sync(0xffffffffu, s, o);
    if ((e & 31) == 0) red[e >> 5] = s;
    __syncthreads();
    if (e == 0) {
        float t = 0.f;
        #pragma unroll
        for (int i = 0; i < 8; i++) t += red[i];
        g_enorm[c] = t;
        g_hist[c]  = 0;
        if (c == 0) g_mse = 0.0;
    }
}

// ---------------------------------------------------------------
// winit: proj weight f16 hi/lo fragments (B operand layout)
// ---------------------------------------------------------------
__global__ void k_winit(const float* __restrict__ w) {
    int c = blockIdx.x;                 // 0..511 (k dim)
    int e = threadIdx.x;                // 0..255 (n dim)
    float v = w[(size_t)e * Cc + c];
    __half h = __float2half_rn(v);
    __half l = __float2half_rn(v - __half2float(h));
    int ks = c >> 4, r = c & 15, kq = (r >> 1) & 3, odd = r & 1, b1f = r >> 3;
    int tn = e >> 3, qq = e & 7;
    int lane = qq * 4 + kq;
    size_t f4 = ((size_t)ks * 32 + tn) * 32 + lane;
    __half* hp = (__half*)g_wf;
    hp[f4 * 8 + b1f * 2 + odd]     = h;
    hp[f4 * 8 + 4 + b1f * 2 + odd] = l;
}

// ---------------------------------------------------------------
// FUSED proj + dist: CTA = 64 tokens, 256 threads (8 warps 2m x 4n), occ 2
// Phase 1 (proj): 32 k16 W-chunks (3-stage ring), A staged in [0,8K) of the
//   A region (dead until epilogue); x fragments written to [0,64K) afterward
// Phase 2 (dist): 64 k16 B-chunks (3-stage ring) over 1024 codes, argmin
// smem: A frags [0,64K) | ring [64K,112K)
// ---------------------------------------------------------------
#define MAIN_DYN (65536 + 3 * 16384)
__global__ void __launch_bounds__(256, 2)
k_main(const float* __restrict__ in, const float* __restrict__ bias) {
    extern __shared__ char dyn[];
    __shared__ float sXn[64];

    int tid  = threadIdx.x;
    int lane = tid & 31, wid = tid >> 5;
    int wm   = wid >> 2, wn = wid & 3;
    int q    = lane >> 2, kq = lane & 3;
    int g    = blockIdx.x;                           // 64-token group
    int n0   = g * 64;
    int b    = n0 >> 12, t0 = n0 & 4095;
    const float* inb = in + (size_t)b * Cc * Tt + t0;
    uint32_t dynu  = smem_u32(dyn);
    uint32_t ringu = dynu + 65536;

    if (tid < 64) sXn[tid] = 0.f;

    // ================= PHASE 1: projection =================
    {
        // W ring (3-stage) at ring[0,48K); A-stage (2 bufs, 8KB) at dyn[0,8K)
        float*  stAf = (float*)dyn;
        float4* stA4 = (float4*)dyn;
        int akq = tid & 3, aq = (tid >> 2) & 7, atm = (tid >> 5) & 3, khalf = tid >> 7;

        #define ISSUE_W(ch) do {                                                      \
            const char* _s = (const char*)((const float4*)g_wf + (size_t)(ch)*1024);  \
            uint32_t _d = ringu + (uint32_t)((ch) % 3) * 16384;                       \
            for (int i = tid; i < 1024; i += 256)                                     \
                cp16(_d + (uint32_t)i * 16, _s + (size_t)i * 16);                     \
            CP_COMMIT();                                                              \
        } while (0)

        #define LDG_A(ch, v) do {                                                     \
            const float* _p = inb + (size_t)((ch) * 16 + khalf * 8 + 2 * akq) * Tt    \
                                  + atm * 16 + aq;                                    \
            (v)[0] = _p[0];  (v)[1] = _p[Tt];                                         \
            (v)[2] = _p[8];  (v)[3] = _p[Tt + 8];                                     \
        } while (0)

        #define STS_A(buf, v) do {                                                    \
            uint32_t _l0, _l1;                                                        \
            uint32_t _h0 = packsplit((v)[0], (v)[1], _l0);                            \
            uint32_t _h1 = packsplit((v)[2], (v)[3], _l1);                            \
            int _o = (buf) * 1024 + (atm * 32 + aq * 4 + akq) * 4 + khalf * 2;        \
            *(uint2*)&stAf[_o]       = make_uint2(_h0, _h1);                          \
            *(uint2*)&stAf[_o + 512] = make_uint2(_l0, _l1);                          \
        } while (0)

        {
            float v[4];
            LDG_A(0, v);
            STS_A(0, v);
        }
        ISSUE_W(0);
        ISSUE_W(1);

        float acc[2][8][4];
        #pragma unroll
        for (int a = 0; a < 2; a++)
            #pragma unroll
            for (int bb = 0; bb < 8; bb++)
                #pragma unroll
                for (int cix = 0; cix < 4; cix++) acc[a][bb][cix] = 0.f;

        for (int ch = 0; ch < 32; ch++) {
            if (ch < 31) CP_WAIT1(); else CP_WAIT0();
            __syncthreads();             // publishes stA[ch&1] + W(ch); retires W(ch-1)
            if (ch + 2 < 32) ISSUE_W(ch + 2);   // stage (ch+2)%3: disjoint from read stage
            float v[4];
            if (ch < 31) LDG_A(ch + 1, v);

            const float4* W4 = (const float4*)(dyn + 65536 + (ch % 3) * 16384);
            uint32_t aH[2][4], aL[2][4];
            #pragma unroll
            for (int mt = 0; mt < 2; mt++) {
                int tmg = wm * 2 + mt;
                float4 h4 = stA4[(ch & 1) * 256 + tmg * 32 + lane];
                float4 l4 = stA4[(ch & 1) * 256 + 128 + tmg * 32 + lane];
                aH[mt][0] = __float_as_uint(h4.x); aH[mt][1] = __float_as_uint(h4.y);
                aH[mt][2] = __float_as_uint(h4.z); aH[mt][3] = __float_as_uint(h4.w);
                aL[mt][0] = __float_as_uint(l4.x); aL[mt][1] = __float_as_uint(l4.y);
                aL[mt][2] = __float_as_uint(l4.z); aL[mt][3] = __float_as_uint(l4.w);
            }
            #pragma unroll
            for (int nt = 0; nt < 8; nt++) {
                int tng = wn * 8 + nt;
                float4 bf = W4[tng * 32 + lane];
                uint32_t bh0 = __float_as_uint(bf.x), bh1 = __float_as_uint(bf.y);
                uint32_t bl0 = __float_as_uint(bf.z), bl1 = __float_as_uint(bf.w);
                #pragma unroll
                for (int mt = 0; mt < 2; mt++) {
                    mmaf16(acc[mt][nt], aH[mt][0], aH[mt][1], aH[mt][2], aH[mt][3], bh0, bh1);
                    mmaf16(acc[mt][nt], aH[mt][0], aH[mt][1], aH[mt][2], aH[mt][3], bl0, bl1);
                    mmaf16(acc[mt][nt], aL[mt][0], aL[mt][1], aL[mt][2], aL[mt][3], bh0, bh1);
                }
            }
            if (ch < 31) STS_A((ch + 1) & 1, v);
        }

        // epilogue: bias, ||x||^2, x fragments -> smem A region [0,64K)
        __syncthreads();                 // all stA/W reads retired; A region writable
        float4* xf4 = (float4*)dyn;
        #pragma unroll
        for (int mt = 0; mt < 2; mt++) {
            int tmg = wm * 2 + mt;
            float xnq = 0.f, xnq8 = 0.f;
            #pragma unroll
            for (int ntp = 0; ntp < 4; ntp++) {   // nt pairs (even, odd)
                int ntE = ntp * 2, ntO = ntp * 2 + 1;
                int eE = wn * 64 + ntE * 8 + 2 * kq;
                int eO = wn * 64 + ntO * 8 + 2 * kq;
                float bE0 = __ldg(&bias[eE]),     bE1 = __ldg(&bias[eE + 1]);
                float bO0 = __ldg(&bias[eO]),     bO1 = __ldg(&bias[eO + 1]);
                float x0 = acc[mt][ntE][0] + bE0;
                float x1 = acc[mt][ntE][1] + bE1;
                float x2 = acc[mt][ntE][2] + bE0;
                float x3 = acc[mt][ntE][3] + bE1;
                float y0 = acc[mt][ntO][0] + bO0;
                float y1 = acc[mt][ntO][1] + bO1;
                float y2 = acc[mt][ntO][2] + bO0;
                float y3 = acc[mt][ntO][3] + bO1;
                xnq  += x0 * x0 + x1 * x1 + y0 * y0 + y1 * y1;
                xnq8 += x2 * x2 + x3 * x3 + y2 * y2 + y3 * y3;
                int ks = wn * 4 + ntp;
                uint32_t l0, l1, l2, l3;
                uint32_t h0 = packsplit(x0, x1, l0);
                uint32_t h1 = packsplit(x2, x3, l1);
                uint32_t h2 = packsplit(y0, y1, l2);
                uint32_t h3 = packsplit(y2, y3, l3);
                int idx = (ks * 4 + tmg) * 32 + lane;
                xf4[idx]        = make_float4(__uint_as_float(h0), __uint_as_float(h1),
                                              __uint_as_float(h2), __uint_as_float(h3));
                xf4[2048 + idx] = make_float4(__uint_as_float(l0), __uint_as_float(l1),
                                              __uint_as_float(l2), __uint_as_float(l3));
            }
            xnq  += __shfl_xor_sync(0xffffffffu, xnq, 1);
            xnq  += __shfl_xor_sync(0xffffffffu, xnq, 2);
            xnq8 += __shfl_xor_sync(0xffffffffu, xnq8, 1);
            xnq8 += __shfl_xor_sync(0xffffffffu, xnq8, 2);
            if (kq == 0) {
                int tl = wm * 32 + mt * 16 + q;
                atomicAdd(&sXn[tl], xnq);
                atomicAdd(&sXn[tl + 8], xnq8);
            }
        }
    }

    // ================= PHASE 2: distance + argmin =================
    const float4* smA = (const float4*)dyn;

    #define ISSUE(cc) do {                                                        \
        int _cgp = (cc) >> 4, _ks = (cc) & 15;                                    \
        const char* _s = (const char*)((const float4*)g_ef +                      \
                          ((size_t)(_cgp * 16 + _ks)) * 1024);                    \
        uint32_t _d = ringu + (uint32_t)((cc) % 3) * 16384;                       \
        for (int i = tid; i < 1024; i += 256)                                     \
            cp16(_d + (uint32_t)i * 16, _s + (size_t)i * 16);                     \
        CP_COMMIT();                                                              \
    } while (0)

    ISSUE(0);
    ISSUE(1);

    float acc[2][8][4];
    #pragma unroll
    for (int a = 0; a < 2; a++)
        #pragma unroll
        for (int b2 = 0; b2 < 8; b2++)
            #pragma unroll
            for (int c = 0; c < 4; c++) acc[a][b2][c] = 0.f;
    float bestv[4]; int besti[4];
    #pragma unroll
    for (int s = 0; s < 4; s++) { bestv[s] = 3.0e38f; besti[s] = 0; }

    for (int cc = 0; cc < 64; cc++) {
        if (cc + 1 < 64) CP_WAIT1(); else CP_WAIT0();
        __syncthreads();                 // publishes buf[cc] (+A frags on cc==0)
        if (cc + 2 < 64) ISSUE(cc + 2);
        const float4* B4 = (const float4*)(dyn + 65536 + (cc % 3) * 16384);
        int ks = cc & 15;
        uint32_t aH[2][4], aL[2][4];
        #pragma unroll
        for (int tm2 = 0; tm2 < 2; tm2++) {
            int tmg = wm * 2 + tm2;
            float4 h4 = smA[(ks * 4 + tmg) * 32 + lane];
            float4 l4 = smA[2048 + (ks * 4 + tmg) * 32 + lane];
            aH[tm2][0] = __float_as_uint(h4.x); aH[tm2][1] = __float_as_uint(h4.y);
            aH[tm2][2] = __float_as_uint(h4.z); aH[tm2][3] = __float_as_uint(h4.w);
            aL[tm2][0] = __float_as_uint(l4.x); aL[tm2][1] = __float_as_uint(l4.y);
            aL[tm2][2] = __float_as_uint(l4.z); aL[tm2][3] = __float_as_uint(l4.w);
        }
        #pragma unroll
        for (int tn = 0; tn < 8; tn++) {
            int tng = wn * 8 + tn;
            float4 bf = B4[tng * 32 + lane];
            uint32_t bh0 = __float_as_uint(bf.x), bh1 = __float_as_uint(bf.y);
            uint32_t bl0 = __float_as_uint(bf.z), bl1 = __float_as_uint(bf.w);
            #pragma unroll
            for (int tm2 = 0; tm2 < 2; tm2++) {
                mmaf16(acc[tm2][tn], aH[tm2][0], aH[tm2][1], aH[tm2][2], aH[tm2][3], bh0, bh1);
                mmaf16(acc[tm2][tn], aH[tm2][0], aH[tm2][1], aH[tm2][2], aH[tm2][3], bl0, bl1);
                mmaf16(acc[tm2][tn], aL[tm2][0], aL[tm2][1], aL[tm2][2], aL[tm2][3], bh0, bh1);
            }
        }
        if (ks == 15) {
            int cgp = cc >> 4;
            #pragma unroll
            for (int tn = 0; tn < 8; tn++) {
                int tng = wn * 8 + tn;
                int nb = cgp * 256 + tng * 8 + 2 * kq;
                float e0v = __ldg(&g_enorm[nb]);
                float e1v = __ldg(&g_enorm[nb + 1]);
                #pragma unroll
                for (int tm2 = 0; tm2 < 2; tm2++) {
                    float s00 = fmaf(-2.0f, acc[tm2][tn][0], e0v);
                    float s01 = fmaf(-2.0f, acc[tm2][tn][1], e1v);
                    float s10 = fmaf(-2.0f, acc[tm2][tn][2], e0v);
                    float s11 = fmaf(-2.0f, acc[tm2][tn][3], e1v);
                    int s0 = tm2 * 2, s1 = tm2 * 2 + 1;
                    if (s00 < bestv[s0]) { bestv[s0] = s00; besti[s0] = nb; }
                    if (s01 < bestv[s0]) { bestv[s0] = s01; besti[s0] = nb + 1; }
                    if (s10 < bestv[s1]) { bestv[s1] = s10; besti[s1] = nb; }
                    if (s11 < bestv[s1]) { bestv[s1] = s11; besti[s1] = nb + 1; }
                    acc[tm2][tn][0] = 0.f; acc[tm2][tn][1] = 0.f;
                    acc[tm2][tn][2] = 0.f; acc[tm2][tn][3] = 0.f;
                }
            }
        }
    }
    __syncthreads();                     // compute done; reuse B ring
    float* redv = (float*)(dyn + 65536);            // 64*4 floats
    int*   redi = (int*)(dyn + 65536 + 1024);       // 64*4 ints
    float* lred = (float*)(dyn + 65536 + 2048);     // 2 floats

    #pragma unroll
    for (int s = 0; s < 4; s++) {
        float v = bestv[s]; int bi = besti[s];
        #pragma unroll
        for (int off = 1; off <= 2; off <<= 1) {
            float ov = __shfl_xor_sync(0xffffffffu, v, off);
            int   oi = __shfl_xor_sync(0xffffffffu, bi, off);
            if (ov < v || (ov == v && oi < bi)) { v = ov; bi = oi; }
        }
        if ((lane & 3) == 0) {
            int row = wm * 32 + (s >> 1) * 16 + (s & 1) * 8 + q;
            redv[row * 4 + wn] = v;
            redi[row * 4 + wn] = bi;
        }
    }
    __syncthreads();
    float myd2 = 0.f;
    if (tid < 64) {
        float v = redv[tid * 4]; int bi = redi[tid * 4];
        #pragma unroll
        for (int j = 1; j < 4; j++) {
            float ov = redv[tid * 4 + j]; int oi = redi[tid * 4 + j];
            if (ov < v || (ov == v && oi < bi)) { v = ov; bi = oi; }
        }
        int n = n0 + tid;
        g_idx[n] = bi;
        atomicAdd(&g_hist[bi], 1);
        myd2 = sXn[tid] + v;                   // ||x||^2 + (||e||^2 - 2x.e)
    }
    for (int o = 16; o > 0; o >>= 1) myd2 += __shfl_down_sync(0xffffffffu, myd2, o);
    if ((tid & 31) == 0 && wid < 2) lred[wid] = myd2;
    __syncthreads();
    if (tid == 0) atomicAdd(&g_mse, (double)(lred[0] + lred[1]));
}

// ---------------------------------------------------------------
// output: z_q_out[b,e,t] = embed[q_idx[b*T+t]][e]  (32x32 transpose)
// ---------------------------------------------------------------
__global__ void k_out(const float* __restrict__ embed, float* __restrict__ out) {
    __shared__ int   qs[32];
    __shared__ float sm[32][33];
    int b  = blockIdx.z;
    int e0 = blockIdx.y * 32;
    int t0 = blockIdx.x * 32;
    int tid = threadIdx.x;
    if (tid < 32) qs[tid] = g_idx[b * Tt + t0 + tid];
    __syncthreads();
    {
        int j = tid >> 3, gg = tid & 7;
        const float4* erow = (const float4*)(embed + (size_t)qs[j] * Ee + e0);
        float4 v = erow[gg];
        sm[j][gg * 4 + 0] = v.x; sm[j][gg * 4 + 1] = v.y;
        sm[j][gg * 4 + 2] = v.z; sm[j][gg * 4 + 3] = v.w;
    }
    __syncthreads();
    int tl = tid & 31, eb = tid >> 5;
    #pragma unroll
    for (int r = 0; r < 4; r++) {
        int el = eb + r * 8;
        out[((size_t)b * Ee + e0 + el) * Tt + t0 + tl] = sm[tl][el];
    }
}

// ---------------------------------------------------------------
// tail scalars
// ---------------------------------------------------------------
__global__ void k_tail(float* __restrict__ out) {
    __shared__ float red[32];
    int tid = threadIdx.x;                     // 1024
    float p = (float)g_hist[tid] / 65536.0f;
    float term = -p * logf(p + 1e-10f);
    for (int o = 16; o > 0; o >>= 1) term += __shfl_down_sync(0xffffffffu, term, o);
    if ((tid & 31) == 0) red[tid >> 5] = term;
    __syncthreads();
    const size_t base = (size_t)Bb * Ee * Tt;
    if (tid == 0) {
        float lp = 0.f;
        #pragma unroll
        for (int i = 0; i < 32; i++) lp += red[i];
        out[base + 0]  = (float)(1.25 * (g_mse / (double)((size_t)NTOK * Ee)));
        out[base + 17] = lp;
    }
    if (tid < 16) out[base + 1 + tid] = (float)(log(1024.0) * 4096.0);
}

// ---------------------------------------------------------------
extern "C" void kernel_launch(void* const* d_in, const int* in_sizes, int n_in,
                              void* d_out, int out_size) {
    const float* inputs = (const float*)d_in[0];   // [16, 512, 4096]
    const float* proj_w = (const float*)d_in[1];   // [256, 512]
    const float* proj_b = (const float*)d_in[2];   // [256]
    const float* embed  = (const float*)d_in[3];   // [1024, 256]
    float* out = (float*)d_out;

    cudaFuncSetAttribute(k_main, cudaFuncAttributeMaxDynamicSharedMemorySize, MAIN_DYN);

    k_init<<<NE, 256>>>(embed);
    k_winit<<<Cc, 256>>>(proj_w);
    k_main<<<NTOK / 64, 256, MAIN_DYN>>>(inputs, proj_b);
    dim3 g3(Tt / 32, Ee / 32, Bb);
    k_out<<<g3, 256>>>(embed, out);
    k_tail<<<1, 1024>>>(out);
}